// round 4
// baseline (speedup 1.0000x reference)
#include <cuda_runtime.h>
#include <cuda_bf16.h>
#include <math.h>

// Problem constants
#define B_   4
#define S_   2048
#define D_   512
#define H_   8
#define DH_  64
#define TOK  (B_ * S_)          // 8192 tokens
#define SCALE_ 0.125f           // 64^-0.5

// ---------------------------------------------------------------------------
// Device scratch (allocation-free rule: __device__ globals)
// ---------------------------------------------------------------------------
__device__ float g_q[TOK * D_];
__device__ float g_k[TOK * D_];
__device__ float g_v[TOK * D_];
__device__ float g_att[TOK * D_];

// ---------------------------------------------------------------------------
// SGEMM: C[M,N] = A[M,K] @ W[K,N] (+ bias), row-major everywhere.
// BM=128, BN=64, BK=16, 256 threads, 8x4 register tile per thread.
// ---------------------------------------------------------------------------
#define GBM 128
#define GBN 64
#define GBK 16

__device__ __forceinline__ void sgemm_body(const float* __restrict__ A,
                                           const float* __restrict__ W,
                                           float* __restrict__ C,
                                           const float* __restrict__ bias,
                                           int K, int N, int bm, int bn)
{
    __shared__ __align__(16) float As[GBK][GBM + 4];   // transposed: As[k][m]
    __shared__ __align__(16) float Bs[GBK][GBN + 4];   // Bs[k][n]

    const int tid = threadIdx.x;
    const int ty  = tid >> 4;      // 0..15  -> rows ty*8 .. ty*8+7
    const int tx  = tid & 15;      // 0..15  -> cols tx*4 .. tx*4+3

    float acc[8][4];
#pragma unroll
    for (int i = 0; i < 8; i++)
#pragma unroll
        for (int j = 0; j < 4; j++) acc[i][j] = 0.f;

    for (int k0 = 0; k0 < K; k0 += GBK) {
        // Load A tile 128x16 (512 float4, 2 per thread), store transposed
#pragma unroll
        for (int i = 0; i < 2; i++) {
            int f   = (tid << 1) + i;          // 0..511
            int row = f >> 2;                  // 0..127
            int c4  = (f & 3) << 2;            // 0,4,8,12
            const float4 v = *reinterpret_cast<const float4*>(
                A + (bm + row) * K + k0 + c4);
            As[c4 + 0][row] = v.x;
            As[c4 + 1][row] = v.y;
            As[c4 + 2][row] = v.z;
            As[c4 + 3][row] = v.w;
        }
        // Load B tile 16x64 (256 float4, 1 per thread)
        {
            int row = tid >> 4;                // 0..15
            int c4  = (tid & 15) << 2;         // 0..60
            *reinterpret_cast<float4*>(&Bs[row][c4]) =
                *reinterpret_cast<const float4*>(W + (k0 + row) * N + bn + c4);
        }
        __syncthreads();

#pragma unroll
        for (int kk = 0; kk < GBK; kk++) {
            float a[8], b[4];
            *reinterpret_cast<float4*>(&a[0]) =
                *reinterpret_cast<const float4*>(&As[kk][ty * 8]);
            *reinterpret_cast<float4*>(&a[4]) =
                *reinterpret_cast<const float4*>(&As[kk][ty * 8 + 4]);
            *reinterpret_cast<float4*>(&b[0]) =
                *reinterpret_cast<const float4*>(&Bs[kk][tx * 4]);
#pragma unroll
            for (int i = 0; i < 8; i++)
#pragma unroll
                for (int j = 0; j < 4; j++)
                    acc[i][j] = fmaf(a[i], b[j], acc[i][j]);
        }
        __syncthreads();
    }

    float bv[4] = {0.f, 0.f, 0.f, 0.f};
    if (bias) {
        float4 t = *reinterpret_cast<const float4*>(bias + bn + tx * 4);
        bv[0] = t.x; bv[1] = t.y; bv[2] = t.z; bv[3] = t.w;
    }
#pragma unroll
    for (int i = 0; i < 8; i++) {
        float4 v;
        v.x = acc[i][0] + bv[0];
        v.y = acc[i][1] + bv[1];
        v.z = acc[i][2] + bv[2];
        v.w = acc[i][3] + bv[3];
        *reinterpret_cast<float4*>(C + (bm + ty * 8 + i) * N + bn + tx * 4) = v;
    }
}

__global__ __launch_bounds__(256) void qkv_kernel(const float* __restrict__ x,
                                                  const float* __restrict__ Wq,
                                                  const float* __restrict__ Wk,
                                                  const float* __restrict__ Wv)
{
    const float* W;
    float* C;
    if (blockIdx.z == 0)      { W = Wq; C = g_q; }
    else if (blockIdx.z == 1) { W = Wk; C = g_k; }
    else                      { W = Wv; C = g_v; }
    sgemm_body(x, W, C, nullptr, D_, D_, blockIdx.x * GBM, blockIdx.y * GBN);
}

__global__ __launch_bounds__(256) void oproj_kernel(const float* __restrict__ Wo,
                                                    const float* __restrict__ bo,
                                                    float* __restrict__ out)
{
    sgemm_body(g_att, Wo, out, bo, D_, D_, blockIdx.x * GBM, blockIdx.y * GBN);
}

// ---------------------------------------------------------------------------
// Flash attention: per block = one (b,h) pair x 64 q-rows.
// Loop over 32 kv-tiles of 64 rows: S = Q@K^T (scaled), online softmax,
// O += P@V staged through smem. Dh = 64.
// Threads: 256 as 16x16; each thread owns a 4x4 tile of S/P and of O.
// ---------------------------------------------------------------------------
#define SMPAD 68   // 64 + 4 floats: keeps 16B alignment, breaks stride-64 conflicts

__global__ __launch_bounds__(256) void attn_kernel()
{
    extern __shared__ __align__(16) float sm[];
    float (*Qs)[SMPAD] = reinterpret_cast<float(*)[SMPAD]>(sm);                 // [d][r]
    float (*Ks)[SMPAD] = reinterpret_cast<float(*)[SMPAD]>(sm + 64 * SMPAD);    // [d][n]
    float (*Vs)[SMPAD] = reinterpret_cast<float(*)[SMPAD]>(sm + 2 * 64 * SMPAD);// [n][d]
    float (*Ps)[SMPAD] = reinterpret_cast<float(*)[SMPAD]>(sm + 3 * 64 * SMPAD);// [n][r]

    const float* __restrict__ gq = g_q;
    const float* __restrict__ gk = g_k;
    const float* __restrict__ gv = g_v;
    float* __restrict__ gout     = g_att;

    const int tid = threadIdx.x;
    const int ty  = tid >> 4;       // 0..15 -> q-rows 4ty..4ty+3
    const int tx  = tid & 15;       // 0..15 -> cols   4tx..4tx+3
    const int b   = blockIdx.y >> 3;
    const int h   = blockIdx.y & 7;
    const int q0  = blockIdx.x * 64;

    // Load Q tile [64 rows x 64 dims], transposed into Qs[d][r]
    {
        const float* qp = gq + ((b * S_ + q0) * D_ + h * DH_);
#pragma unroll
        for (int i = 0; i < 4; i++) {
            int f   = i * 256 + tid;       // 0..1023
            int row = f >> 4;              // 0..63
            int c4  = (f & 15) << 2;       // 0..60
            float4 v = *reinterpret_cast<const float4*>(qp + row * D_ + c4);
            Qs[c4 + 0][row] = v.x;
            Qs[c4 + 1][row] = v.y;
            Qs[c4 + 2][row] = v.z;
            Qs[c4 + 3][row] = v.w;
        }
    }

    float o[4][4];
#pragma unroll
    for (int i = 0; i < 4; i++)
#pragma unroll
        for (int j = 0; j < 4; j++) o[i][j] = 0.f;
    float mrow[4] = {-1e30f, -1e30f, -1e30f, -1e30f};
    float lrow[4] = {0.f, 0.f, 0.f, 0.f};

    for (int kt = 0; kt < S_ / 64; kt++) {
        __syncthreads();   // protect Ks/Vs/Ps of previous iteration
        {
            const float* kp = gk + ((b * S_ + kt * 64) * D_ + h * DH_);
            const float* vp = gv + ((b * S_ + kt * 64) * D_ + h * DH_);
#pragma unroll
            for (int i = 0; i < 4; i++) {
                int f   = i * 256 + tid;
                int row = f >> 4;
                int c4  = (f & 15) << 2;
                float4 kv = *reinterpret_cast<const float4*>(kp + row * D_ + c4);
                Ks[c4 + 0][row] = kv.x;
                Ks[c4 + 1][row] = kv.y;
                Ks[c4 + 2][row] = kv.z;
                Ks[c4 + 3][row] = kv.w;
                float4 vv = *reinterpret_cast<const float4*>(vp + row * D_ + c4);
                *reinterpret_cast<float4*>(&Vs[row][c4]) = vv;
            }
        }
        __syncthreads();

        // S = Q @ K^T  (4x4 per thread)
        float s[4][4];
#pragma unroll
        for (int i = 0; i < 4; i++)
#pragma unroll
            for (int j = 0; j < 4; j++) s[i][j] = 0.f;

#pragma unroll 16
        for (int d = 0; d < DH_; d++) {
            float4 qa = *reinterpret_cast<const float4*>(&Qs[d][ty << 2]);
            float4 kb = *reinterpret_cast<const float4*>(&Ks[d][tx << 2]);
            float a4[4] = {qa.x, qa.y, qa.z, qa.w};
            float b4[4] = {kb.x, kb.y, kb.z, kb.w};
#pragma unroll
            for (int i = 0; i < 4; i++)
#pragma unroll
                for (int j = 0; j < 4; j++)
                    s[i][j] = fmaf(a4[i], b4[j], s[i][j]);
        }

        // scale + online softmax (row groups of 16 lanes: xor 1,2,4,8)
#pragma unroll
        for (int i = 0; i < 4; i++)
#pragma unroll
            for (int j = 0; j < 4; j++) s[i][j] *= SCALE_;

        float mnew[4], alpha[4];
#pragma unroll
        for (int i = 0; i < 4; i++) {
            float mx = fmaxf(fmaxf(s[i][0], s[i][1]), fmaxf(s[i][2], s[i][3]));
            mx = fmaxf(mx, __shfl_xor_sync(0xffffffffu, mx, 1));
            mx = fmaxf(mx, __shfl_xor_sync(0xffffffffu, mx, 2));
            mx = fmaxf(mx, __shfl_xor_sync(0xffffffffu, mx, 4));
            mx = fmaxf(mx, __shfl_xor_sync(0xffffffffu, mx, 8));
            mnew[i]  = fmaxf(mrow[i], mx);
            alpha[i] = __expf(mrow[i] - mnew[i]);
            mrow[i]  = mnew[i];
        }
#pragma unroll
        for (int i = 0; i < 4; i++) {
#pragma unroll
            for (int j = 0; j < 4; j++)
                s[i][j] = __expf(s[i][j] - mnew[i]);
            float rs = s[i][0] + s[i][1] + s[i][2] + s[i][3];
            rs += __shfl_xor_sync(0xffffffffu, rs, 1);
            rs += __shfl_xor_sync(0xffffffffu, rs, 2);
            rs += __shfl_xor_sync(0xffffffffu, rs, 4);
            rs += __shfl_xor_sync(0xffffffffu, rs, 8);
            lrow[i] = lrow[i] * alpha[i] + rs;
#pragma unroll
            for (int j = 0; j < 4; j++) o[i][j] *= alpha[i];
        }

        // stage P transposed: Ps[n][r]
#pragma unroll
        for (int i = 0; i < 4; i++)
#pragma unroll
            for (int j = 0; j < 4; j++)
                Ps[(tx << 2) + j][(ty << 2) + i] = s[i][j];
        __syncthreads();

        // O += P @ V (4x4 per thread)
#pragma unroll 16
        for (int n = 0; n < 64; n++) {
            float4 pa = *reinterpret_cast<const float4*>(&Ps[n][ty << 2]);
            float4 vb = *reinterpret_cast<const float4*>(&Vs[n][tx << 2]);
            float p4[4] = {pa.x, pa.y, pa.z, pa.w};
            float v4[4] = {vb.x, vb.y, vb.z, vb.w};
#pragma unroll
            for (int i = 0; i < 4; i++)
#pragma unroll
                for (int j = 0; j < 4; j++)
                    o[i][j] = fmaf(p4[i], v4[j], o[i][j]);
        }
    }

    // epilogue: O / l -> g_att (same [token, h*64+d] layout as projections)
    float* op = gout + ((b * S_ + q0) * D_ + h * DH_);
#pragma unroll
    for (int i = 0; i < 4; i++) {
        float inv = 1.0f / lrow[i];
        float4 v = make_float4(o[i][0] * inv, o[i][1] * inv,
                               o[i][2] * inv, o[i][3] * inv);
        *reinterpret_cast<float4*>(op + ((ty << 2) + i) * D_ + (tx << 2)) = v;
    }
}

#define ATTN_SMEM (4 * 64 * SMPAD * (int)sizeof(float))   // 69632 bytes

// ---------------------------------------------------------------------------
// Launch
// ---------------------------------------------------------------------------
extern "C" void kernel_launch(void* const* d_in, const int* in_sizes, int n_in,
                              void* d_out, int out_size)
{
    const float* x  = (const float*)d_in[0];
    const float* Wq = (const float*)d_in[1];
    const float* Wk = (const float*)d_in[2];
    const float* Wv = (const float*)d_in[3];
    const float* Wo = (const float*)d_in[4];
    const float* bo = (const float*)d_in[5];
    float* out = (float*)d_out;

    // 1) fused QKV projections
    dim3 gQKV(TOK / GBM, D_ / GBN, 3);   // (64, 8, 3)
    qkv_kernel<<<gQKV, 256>>>(x, Wq, Wk, Wv);

    // 2) flash attention (needs >48KB dynamic smem)
    cudaFuncSetAttribute(attn_kernel,
                         cudaFuncAttributeMaxDynamicSharedMemorySize, ATTN_SMEM);
    dim3 gATT(S_ / 64, B_ * H_);         // (32, 32)
    attn_kernel<<<gATT, 256, ATTN_SMEM>>>();

    // 3) output projection + bias
    dim3 gO(TOK / GBM, D_ / GBN);        // (64, 8)
    oproj_kernel<<<gO, 256>>>(Wo, bo, out);
}

// round 6
// speedup vs baseline: 1.0010x; 1.0010x over previous
#include <cuda_runtime.h>
#include <cuda_bf16.h>
#include <math.h>

// Problem constants
#define B_   4
#define S_   2048
#define D_   512
#define H_   8
#define DH_  64
#define TOK  (B_ * S_)          // 8192 tokens
#define SCALE_ 0.125f           // 64^-0.5

// ---------------------------------------------------------------------------
// Device scratch (allocation-free rule: __device__ globals)
// ---------------------------------------------------------------------------
__device__ float g_q[TOK * D_];
__device__ float g_k[TOK * D_];
__device__ float g_v[TOK * D_];
__device__ float g_att[TOK * D_];

// ---------------------------------------------------------------------------
// SGEMM: C[M,N] = A[M,K] @ W[K,N] (+ bias), row-major everywhere.
// BM=128, BN=64, BK=16, 256 threads, 8x4 register tile per thread.
// ---------------------------------------------------------------------------
#define GBM 128
#define GBN 64
#define GBK 16

__device__ __forceinline__ void sgemm_body(const float* __restrict__ A,
                                           const float* __restrict__ W,
                                           float* __restrict__ C,
                                           const float* __restrict__ bias,
                                           int K, int N, int bm, int bn)
{
    __shared__ __align__(16) float As[GBK][GBM + 4];   // transposed: As[k][m]
    __shared__ __align__(16) float Bs[GBK][GBN + 4];   // Bs[k][n]

    const int tid = threadIdx.x;
    const int ty  = tid >> 4;      // 0..15  -> rows ty*8 .. ty*8+7
    const int tx  = tid & 15;      // 0..15  -> cols tx*4 .. tx*4+3

    float acc[8][4];
#pragma unroll
    for (int i = 0; i < 8; i++)
#pragma unroll
        for (int j = 0; j < 4; j++) acc[i][j] = 0.f;

    for (int k0 = 0; k0 < K; k0 += GBK) {
        // Load A tile 128x16 (512 float4, 2 per thread), store transposed
#pragma unroll
        for (int i = 0; i < 2; i++) {
            int f   = (tid << 1) + i;          // 0..511
            int row = f >> 2;                  // 0..127
            int c4  = (f & 3) << 2;            // 0,4,8,12
            const float4 v = *reinterpret_cast<const float4*>(
                A + (bm + row) * K + k0 + c4);
            As[c4 + 0][row] = v.x;
            As[c4 + 1][row] = v.y;
            As[c4 + 2][row] = v.z;
            As[c4 + 3][row] = v.w;
        }
        // Load B tile 16x64 (256 float4, 1 per thread)
        {
            int row = tid >> 4;                // 0..15
            int c4  = (tid & 15) << 2;         // 0..60
            *reinterpret_cast<float4*>(&Bs[row][c4]) =
                *reinterpret_cast<const float4*>(W + (k0 + row) * N + bn + c4);
        }
        __syncthreads();

#pragma unroll
        for (int kk = 0; kk < GBK; kk++) {
            float a[8], b[4];
            *reinterpret_cast<float4*>(&a[0]) =
                *reinterpret_cast<const float4*>(&As[kk][ty * 8]);
            *reinterpret_cast<float4*>(&a[4]) =
                *reinterpret_cast<const float4*>(&As[kk][ty * 8 + 4]);
            *reinterpret_cast<float4*>(&b[0]) =
                *reinterpret_cast<const float4*>(&Bs[kk][tx * 4]);
#pragma unroll
            for (int i = 0; i < 8; i++)
#pragma unroll
                for (int j = 0; j < 4; j++)
                    acc[i][j] = fmaf(a[i], b[j], acc[i][j]);
        }
        __syncthreads();
    }

    float bv[4] = {0.f, 0.f, 0.f, 0.f};
    if (bias) {
        float4 t = *reinterpret_cast<const float4*>(bias + bn + tx * 4);
        bv[0] = t.x; bv[1] = t.y; bv[2] = t.z; bv[3] = t.w;
    }
#pragma unroll
    for (int i = 0; i < 8; i++) {
        float4 v;
        v.x = acc[i][0] + bv[0];
        v.y = acc[i][1] + bv[1];
        v.z = acc[i][2] + bv[2];
        v.w = acc[i][3] + bv[3];
        *reinterpret_cast<float4*>(C + (bm + ty * 8 + i) * N + bn + tx * 4) = v;
    }
}

__global__ __launch_bounds__(256) void qkv_kernel(const float* __restrict__ x,
                                                  const float* __restrict__ Wq,
                                                  const float* __restrict__ Wk,
                                                  const float* __restrict__ Wv)
{
    const float* W;
    float* C;
    if (blockIdx.z == 0)      { W = Wq; C = g_q; }
    else if (blockIdx.z == 1) { W = Wk; C = g_k; }
    else                      { W = Wv; C = g_v; }
    sgemm_body(x, W, C, nullptr, D_, D_, blockIdx.x * GBM, blockIdx.y * GBN);
}

__global__ __launch_bounds__(256) void oproj_kernel(const float* __restrict__ Wo,
                                                    const float* __restrict__ bo,
                                                    float* __restrict__ out)
{
    sgemm_body(g_att, Wo, out, bo, D_, D_, blockIdx.x * GBM, blockIdx.y * GBN);
}

// ---------------------------------------------------------------------------
// Flash attention: per block = one (b,h) pair x 64 q-rows.
// Loop over 32 kv-tiles of 64 rows: S = Q@K^T (scaled), online softmax,
// O += P@V staged through smem. Dh = 64.
// Threads: 256 as 16x16; each thread owns a 4x4 tile of S/P and of O.
// ---------------------------------------------------------------------------
#define SMPAD 68   // 64 + 4 floats: keeps 16B alignment, breaks stride-64 conflicts

__global__ __launch_bounds__(256) void attn_kernel()
{
    extern __shared__ __align__(16) float sm[];
    float (*Qs)[SMPAD] = reinterpret_cast<float(*)[SMPAD]>(sm);                 // [d][r]
    float (*Ks)[SMPAD] = reinterpret_cast<float(*)[SMPAD]>(sm + 64 * SMPAD);    // [d][n]
    float (*Vs)[SMPAD] = reinterpret_cast<float(*)[SMPAD]>(sm + 2 * 64 * SMPAD);// [n][d]
    float (*Ps)[SMPAD] = reinterpret_cast<float(*)[SMPAD]>(sm + 3 * 64 * SMPAD);// [n][r]

    const float* __restrict__ gq = g_q;
    const float* __restrict__ gk = g_k;
    const float* __restrict__ gv = g_v;
    float* __restrict__ gout     = g_att;

    const int tid = threadIdx.x;
    const int ty  = tid >> 4;       // 0..15 -> q-rows 4ty..4ty+3
    const int tx  = tid & 15;       // 0..15 -> cols   4tx..4tx+3
    const int b   = blockIdx.y >> 3;
    const int h   = blockIdx.y & 7;
    const int q0  = blockIdx.x * 64;

    // Load Q tile [64 rows x 64 dims], transposed into Qs[d][r]
    {
        const float* qp = gq + ((b * S_ + q0) * D_ + h * DH_);
#pragma unroll
        for (int i = 0; i < 4; i++) {
            int f   = i * 256 + tid;       // 0..1023
            int row = f >> 4;              // 0..63
            int c4  = (f & 15) << 2;       // 0..60
            float4 v = *reinterpret_cast<const float4*>(qp + row * D_ + c4);
            Qs[c4 + 0][row] = v.x;
            Qs[c4 + 1][row] = v.y;
            Qs[c4 + 2][row] = v.z;
            Qs[c4 + 3][row] = v.w;
        }
    }

    float o[4][4];
#pragma unroll
    for (int i = 0; i < 4; i++)
#pragma unroll
        for (int j = 0; j < 4; j++) o[i][j] = 0.f;
    float mrow[4] = {-1e30f, -1e30f, -1e30f, -1e30f};
    float lrow[4] = {0.f, 0.f, 0.f, 0.f};

    for (int kt = 0; kt < S_ / 64; kt++) {
        __syncthreads();   // protect Ks/Vs/Ps of previous iteration
        {
            const float* kp = gk + ((b * S_ + kt * 64) * D_ + h * DH_);
            const float* vp = gv + ((b * S_ + kt * 64) * D_ + h * DH_);
#pragma unroll
            for (int i = 0; i < 4; i++) {
                int f   = i * 256 + tid;
                int row = f >> 4;
                int c4  = (f & 15) << 2;
                float4 kv = *reinterpret_cast<const float4*>(kp + row * D_ + c4);
                Ks[c4 + 0][row] = kv.x;
                Ks[c4 + 1][row] = kv.y;
                Ks[c4 + 2][row] = kv.z;
                Ks[c4 + 3][row] = kv.w;
                float4 vv = *reinterpret_cast<const float4*>(vp + row * D_ + c4);
                *reinterpret_cast<float4*>(&Vs[row][c4]) = vv;
            }
        }
        __syncthreads();

        // S = Q @ K^T  (4x4 per thread)
        float s[4][4];
#pragma unroll
        for (int i = 0; i < 4; i++)
#pragma unroll
            for (int j = 0; j < 4; j++) s[i][j] = 0.f;

#pragma unroll 16
        for (int d = 0; d < DH_; d++) {
            float4 qa = *reinterpret_cast<const float4*>(&Qs[d][ty << 2]);
            float4 kb = *reinterpret_cast<const float4*>(&Ks[d][tx << 2]);
            float a4[4] = {qa.x, qa.y, qa.z, qa.w};
            float b4[4] = {kb.x, kb.y, kb.z, kb.w};
#pragma unroll
            for (int i = 0; i < 4; i++)
#pragma unroll
                for (int j = 0; j < 4; j++)
                    s[i][j] = fmaf(a4[i], b4[j], s[i][j]);
        }

        // scale + online softmax (row groups of 16 lanes: xor 1,2,4,8)
#pragma unroll
        for (int i = 0; i < 4; i++)
#pragma unroll
            for (int j = 0; j < 4; j++) s[i][j] *= SCALE_;

        float mnew[4], alpha[4];
#pragma unroll
        for (int i = 0; i < 4; i++) {
            float mx = fmaxf(fmaxf(s[i][0], s[i][1]), fmaxf(s[i][2], s[i][3]));
            mx = fmaxf(mx, __shfl_xor_sync(0xffffffffu, mx, 1));
            mx = fmaxf(mx, __shfl_xor_sync(0xffffffffu, mx, 2));
            mx = fmaxf(mx, __shfl_xor_sync(0xffffffffu, mx, 4));
            mx = fmaxf(mx, __shfl_xor_sync(0xffffffffu, mx, 8));
            mnew[i]  = fmaxf(mrow[i], mx);
            alpha[i] = __expf(mrow[i] - mnew[i]);
            mrow[i]  = mnew[i];
        }
#pragma unroll
        for (int i = 0; i < 4; i++) {
#pragma unroll
            for (int j = 0; j < 4; j++)
                s[i][j] = __expf(s[i][j] - mnew[i]);
            float rs = s[i][0] + s[i][1] + s[i][2] + s[i][3];
            rs += __shfl_xor_sync(0xffffffffu, rs, 1);
            rs += __shfl_xor_sync(0xffffffffu, rs, 2);
            rs += __shfl_xor_sync(0xffffffffu, rs, 4);
            rs += __shfl_xor_sync(0xffffffffu, rs, 8);
            lrow[i] = lrow[i] * alpha[i] + rs;
#pragma unroll
            for (int j = 0; j < 4; j++) o[i][j] *= alpha[i];
        }

        // stage P transposed: Ps[n][r]
#pragma unroll
        for (int i = 0; i < 4; i++)
#pragma unroll
            for (int j = 0; j < 4; j++)
                Ps[(tx << 2) + j][(ty << 2) + i] = s[i][j];
        __syncthreads();

        // O += P @ V (4x4 per thread)
#pragma unroll 16
        for (int n = 0; n < 64; n++) {
            float4 pa = *reinterpret_cast<const float4*>(&Ps[n][ty << 2]);
            float4 vb = *reinterpret_cast<const float4*>(&Vs[n][tx << 2]);
            float p4[4] = {pa.x, pa.y, pa.z, pa.w};
            float v4[4] = {vb.x, vb.y, vb.z, vb.w};
#pragma unroll
            for (int i = 0; i < 4; i++)
#pragma unroll
                for (int j = 0; j < 4; j++)
                    o[i][j] = fmaf(p4[i], v4[j], o[i][j]);
        }
    }

    // epilogue: O / l -> g_att (same [token, h*64+d] layout as projections)
    float* op = gout + ((b * S_ + q0) * D_ + h * DH_);
#pragma unroll
    for (int i = 0; i < 4; i++) {
        float inv = 1.0f / lrow[i];
        float4 v = make_float4(o[i][0] * inv, o[i][1] * inv,
                               o[i][2] * inv, o[i][3] * inv);
        *reinterpret_cast<float4*>(op + ((ty << 2) + i) * D_ + (tx << 2)) = v;
    }
}

#define ATTN_SMEM (4 * 64 * SMPAD * (int)sizeof(float))   // 69632 bytes

// ---------------------------------------------------------------------------
// Launch
// ---------------------------------------------------------------------------
extern "C" void kernel_launch(void* const* d_in, const int* in_sizes, int n_in,
                              void* d_out, int out_size)
{
    const float* x  = (const float*)d_in[0];
    const float* Wq = (const float*)d_in[1];
    const float* Wk = (const float*)d_in[2];
    const float* Wv = (const float*)d_in[3];
    const float* Wo = (const float*)d_in[4];
    const float* bo = (const float*)d_in[5];
    float* out = (float*)d_out;

    // 1) fused QKV projections
    dim3 gQKV(TOK / GBM, D_ / GBN, 3);   // (64, 8, 3)
    qkv_kernel<<<gQKV, 256>>>(x, Wq, Wk, Wv);

    // 2) flash attention (needs >48KB dynamic smem)
    cudaFuncSetAttribute(attn_kernel,
                         cudaFuncAttributeMaxDynamicSharedMemorySize, ATTN_SMEM);
    dim3 gATT(S_ / 64, B_ * H_);         // (32, 32)
    attn_kernel<<<gATT, 256, ATTN_SMEM>>>();

    // 3) output projection + bias
    dim3 gO(TOK / GBM, D_ / GBN);        // (64, 8)
    oproj_kernel<<<gO, 256>>>(Wo, bo, out);
}

// round 10
// speedup vs baseline: 2.3395x; 2.3371x over previous
#include <cuda_runtime.h>
#include <cuda_bf16.h>
#include <cstdint>

#define B_ 4
#define S_ 2048
#define D_ 512
#define TOK (B_*S_)
#define SCALE_ 0.125f

// ------------------------- device scratch ---------------------------------
__device__ __nv_bfloat16 g_x_hi[TOK*D_],  g_x_lo[TOK*D_];
__device__ __nv_bfloat16 g_wt_hi[4*D_*D_], g_wt_lo[4*D_*D_];   // [n][k]
__device__ __nv_bfloat16 g_q_hi[TOK*D_],  g_q_lo[TOK*D_];
__device__ __nv_bfloat16 g_k_hi[TOK*D_],  g_k_lo[TOK*D_];
__device__ __nv_bfloat16 g_vt_hi[TOK*D_], g_vt_lo[TOK*D_];     // [b,h,d,S]
__device__ __nv_bfloat16 g_att_hi[TOK*D_], g_att_lo[TOK*D_];

// ------------------------- PTX helpers ------------------------------------
__device__ __forceinline__ uint32_t smem_u32(const void* p) {
    uint32_t a;
    asm("{ .reg .u64 t; cvta.to.shared.u64 t, %1; cvt.u32.u64 %0, t; }"
        : "=r"(a) : "l"(p));
    return a;
}
#define CP_ASYNC(d, s) asm volatile("cp.async.cg.shared.global [%0], [%1], 16;" :: "r"(d), "l"(s) : "memory")
#define CP_COMMIT()    asm volatile("cp.async.commit_group;" ::: "memory")
#define CP_WAIT(n)     asm volatile("cp.async.wait_group %0;" :: "n"(n) : "memory")

__device__ __forceinline__ void ldsm4(uint32_t* r, uint32_t a) {
    asm volatile("ldmatrix.sync.aligned.m8n8.x4.shared.b16 {%0,%1,%2,%3}, [%4];"
        : "=r"(r[0]), "=r"(r[1]), "=r"(r[2]), "=r"(r[3]) : "r"(a));
}
__device__ __forceinline__ void mma16816(float* c, const uint32_t* a, const uint32_t* b) {
    asm volatile("mma.sync.aligned.m16n8k16.row.col.f32.bf16.bf16.f32 "
        "{%0,%1,%2,%3}, {%4,%5,%6,%7}, {%8,%9}, {%0,%1,%2,%3};"
        : "+f"(c[0]), "+f"(c[1]), "+f"(c[2]), "+f"(c[3])
        : "r"(a[0]), "r"(a[1]), "r"(a[2]), "r"(a[3]), "r"(b[0]), "r"(b[1]));
}
__device__ __forceinline__ float fast_ex2(float x) {
    float y; asm("ex2.approx.f32 %0, %1;" : "=f"(y) : "f"(x)); return y;
}
__device__ __forceinline__ void split2(float f0, float f1, uint32_t& h, uint32_t& l) {
    __nv_bfloat16 h0 = __float2bfloat16(f0), h1 = __float2bfloat16(f1);
    __nv_bfloat16 l0 = __float2bfloat16(f0 - __bfloat162float(h0));
    __nv_bfloat16 l1 = __float2bfloat16(f1 - __bfloat162float(h1));
    __nv_bfloat162 th = __halves2bfloat162(h0, h1), tl = __halves2bfloat162(l0, l1);
    h = *reinterpret_cast<uint32_t*>(&th);
    l = *reinterpret_cast<uint32_t*>(&tl);
}
// 64 strided floats -> 64 bf16 hi + 64 bf16 lo (vectorized 16B stores)
__device__ __forceinline__ void row64_hi_lo(const float* src, int stride,
                                            __nv_bfloat16* oh, __nv_bfloat16* ol) {
#pragma unroll
    for (int g = 0; g < 8; g++) {
        uint32_t hh[4], ll[4];
#pragma unroll
        for (int p = 0; p < 4; p++)
            split2(src[(g*8 + p*2) * stride], src[(g*8 + p*2 + 1) * stride], hh[p], ll[p]);
        *reinterpret_cast<uint4*>(oh + g*8) = make_uint4(hh[0], hh[1], hh[2], hh[3]);
        *reinterpret_cast<uint4*>(ol + g*8) = make_uint4(ll[0], ll[1], ll[2], ll[3]);
    }
}

// ------------------------- prep kernels -----------------------------------
__global__ __launch_bounds__(256) void cvt_x(const float* __restrict__ x) {
    size_t i = ((size_t)blockIdx.x * 256 + threadIdx.x) * 4;
    float4 v = *reinterpret_cast<const float4*>(x + i);
    uint32_t h0, l0, h1, l1;
    split2(v.x, v.y, h0, l0);
    split2(v.z, v.w, h1, l1);
    *reinterpret_cast<uint2*>(g_x_hi + i) = make_uint2(h0, h1);
    *reinterpret_cast<uint2*>(g_x_lo + i) = make_uint2(l0, l1);
}

__global__ __launch_bounds__(256) void cvt_w(const float* __restrict__ Wq,
                                             const float* __restrict__ Wk,
                                             const float* __restrict__ Wv,
                                             const float* __restrict__ Wo) {
    __shared__ float t[32][33];
    const int z = blockIdx.z;
    const float* W = (z == 0) ? Wq : (z == 1) ? Wk : (z == 2) ? Wv : Wo;
    const int k0 = blockIdx.x * 32, n0 = blockIdx.y * 32;
    const int tx = threadIdx.x & 31, ty = threadIdx.x >> 5;
#pragma unroll
    for (int r = 0; r < 4; r++)
        t[ty + r * 8][tx] = W[(size_t)(k0 + ty + r * 8) * D_ + n0 + tx];
    __syncthreads();
#pragma unroll
    for (int r = 0; r < 4; r++) {
        int nn = ty + r * 8;
        float f = t[tx][nn];
        __nv_bfloat16 h = __float2bfloat16(f);
        size_t oi = (size_t)z * D_ * D_ + (size_t)(n0 + nn) * D_ + k0 + tx;
        g_wt_hi[oi] = h;
        g_wt_lo[oi] = __float2bfloat16(f - __bfloat162float(h));
    }
}

// ------------------------- HMMA GEMM --------------------------------------
// C[8192,512] = A @ W, block 128x128, warp 64x32, k-chunks of 32, split-bf16
// 3-pass. smem: per buf {Ah,Al,Bh,Bl} 128x(80B pitch). modes: 0=Q 1=K 2=V(T) 3=O
#define GSM 81920

__global__ __launch_bounds__(256, 2) void gemm_mma(int mode_base,
                                                   const float* __restrict__ bias,
                                                   float* __restrict__ out) {
    extern __shared__ char sm[];
    const int tid = threadIdx.x, lane = tid & 31, w = tid >> 5;
    const int wm = w & 1, wn = w >> 1;
    const int mode = mode_base + blockIdx.z;
    const int m0 = blockIdx.x * 128, n0 = blockIdx.y * 128;
    const uint32_t sb = smem_u32(sm);

    const __nv_bfloat16* Ah = ((mode < 3) ? g_x_hi : g_att_hi) + (size_t)m0 * D_;
    const __nv_bfloat16* Al = ((mode < 3) ? g_x_lo : g_att_lo) + (size_t)m0 * D_;
    const __nv_bfloat16* Bh = g_wt_hi + (size_t)mode * D_ * D_ + (size_t)n0 * D_;
    const __nv_bfloat16* Bl = g_wt_lo + (size_t)mode * D_ * D_ + (size_t)n0 * D_;

    float acc[4][4][4];
#pragma unroll
    for (int i = 0; i < 4; i++)
#pragma unroll
        for (int j = 0; j < 4; j++)
#pragma unroll
            for (int k = 0; k < 4; k++) acc[i][j][k] = 0.f;

    const int lr = tid >> 1, sgb = (tid & 1) * 2;
    auto load_chunk = [&](int buf, int k0) {
        uint32_t d = sb + buf * 40960 + lr * 80 + sgb * 16;
        const size_t so = (size_t)lr * D_ + k0 + sgb * 8;
#pragma unroll
        for (int j = 0; j < 2; j++) {
            CP_ASYNC(d + j * 16,         Ah + so + j * 8);
            CP_ASYNC(d + 10240 + j * 16, Al + so + j * 8);
            CP_ASYNC(d + 20480 + j * 16, Bh + so + j * 8);
            CP_ASYNC(d + 30720 + j * 16, Bl + so + j * 8);
        }
    };

    load_chunk(0, 0); CP_COMMIT();
    const uint32_t arow = (uint32_t)(wm * 64 + (lane & 15)) * 80 + (lane >> 4) * 16;
    const uint32_t brow = (uint32_t)(wn * 32 + ((lane >> 4) & 1) * 8 + (lane & 7)) * 80
                          + ((lane >> 3) & 1) * 16;

    for (int c = 0; c < 16; c++) {
        if (c < 15) { load_chunk((c + 1) & 1, (c + 1) * 32); CP_COMMIT(); CP_WAIT(1); }
        else CP_WAIT(0);
        __syncthreads();
        const uint32_t base = sb + (c & 1) * 40960;
#pragma unroll
        for (int kk = 0; kk < 2; kk++) {
            uint32_t bh[2][4], bl[2][4];
#pragma unroll
            for (int nt2 = 0; nt2 < 2; nt2++) {
                uint32_t ba = base + 20480 + brow + nt2 * 16 * 80 + kk * 32;
                ldsm4(bh[nt2], ba);
                ldsm4(bl[nt2], ba + 10240);
            }
#pragma unroll
            for (int mt = 0; mt < 4; mt++) {
                uint32_t aa = base + arow + mt * 16 * 80 + kk * 32;
                uint32_t ah[4], al[4];
                ldsm4(ah, aa);
                ldsm4(al, aa + 10240);
#pragma unroll
                for (int nt2 = 0; nt2 < 2; nt2++) {
                    mma16816(acc[mt][nt2 * 2],     ah, &bh[nt2][0]);
                    mma16816(acc[mt][nt2 * 2],     al, &bh[nt2][0]);
                    mma16816(acc[mt][nt2 * 2],     ah, &bl[nt2][0]);
                    mma16816(acc[mt][nt2 * 2 + 1], ah, &bh[nt2][2]);
                    mma16816(acc[mt][nt2 * 2 + 1], al, &bh[nt2][2]);
                    mma16816(acc[mt][nt2 * 2 + 1], ah, &bl[nt2][2]);
                }
            }
        }
        __syncthreads();
    }

    // stage C into smem [128][132] f32, then mode-specific vectorized writes
    float* cs = reinterpret_cast<float*>(sm);
    {
        const int rr = wm * 64 + (lane >> 2), cc = wn * 32 + 2 * (lane & 3);
#pragma unroll
        for (int mt = 0; mt < 4; mt++)
#pragma unroll
            for (int nt = 0; nt < 4; nt++) {
                int r0 = rr + mt * 16, c0 = cc + nt * 8;
                cs[r0 * 132 + c0]           = acc[mt][nt][0];
                cs[r0 * 132 + c0 + 1]       = acc[mt][nt][1];
                cs[(r0 + 8) * 132 + c0]     = acc[mt][nt][2];
                cs[(r0 + 8) * 132 + c0 + 1] = acc[mt][nt][3];
            }
    }
    __syncthreads();

    if (mode <= 1) {
        int r = tid >> 1, hf = tid & 1;
        size_t ob = (size_t)(m0 + r) * D_ + n0 + hf * 64;
        row64_hi_lo(cs + r * 132 + hf * 64, 1,
                    (mode ? g_k_hi : g_q_hi) + ob, (mode ? g_k_lo : g_q_lo) + ob);
    } else if (mode == 3) {
        int r = tid >> 1, hf = tid & 1;
        float* op = out + (size_t)(m0 + r) * D_ + n0 + hf * 64;
        const float* sp = cs + r * 132 + hf * 64;
        const float* bp = bias + n0 + hf * 64;
#pragma unroll
        for (int g = 0; g < 16; g++) {
            float4 v;
            v.x = sp[g * 4 + 0] + bp[g * 4 + 0];
            v.y = sp[g * 4 + 1] + bp[g * 4 + 1];
            v.z = sp[g * 4 + 2] + bp[g * 4 + 2];
            v.w = sp[g * 4 + 3] + bp[g * 4 + 3];
            *reinterpret_cast<float4*>(op + g * 4) = v;
        }
    } else {   // V: transpose -> [b,h,d,S]
        int dl = tid >> 1, sh = tid & 1;
        int dg = n0 + dl, hh = dg >> 6, dd = dg & 63, bb = m0 >> 11;
        size_t ob = ((size_t)(bb * 8 + hh) * 64 + dd) * (size_t)S_ + (m0 & 2047) + sh * 64;
        row64_hi_lo(cs + (sh * 64) * 132 + dl, 132, g_vt_hi + ob, g_vt_lo + ob);
    }
}

// ------------------------- attention --------------------------------------
// CTA = 128 q-rows x (b,h). Warp owns 16 q-rows x full 128-kv S tile.
// S frags (f32) -> exp (ex2) -> P hi/lo A-frags in-register -> O += 3-pass PV.
// Unnormalized O accumulation, register row sums, normalize at epilogue.
#define AQH 0
#define AQL 18432
#define AKH0 36864      /* + buf*36864 ; KL = +18432 */
#define AVH0 110592     /* + buf*34816 ; VL = +17408 */
#define ASMB 180224

__global__ __launch_bounds__(256) void attn_mma() {
    extern __shared__ char sm[];
    const int tid = threadIdx.x, lane = tid & 31, w = tid >> 5;
    const int qt = blockIdx.x, b = blockIdx.y >> 3, h = blockIdx.y & 7;
    const uint32_t sb = smem_u32(sm);

    const size_t qrow  = (size_t)(b * S_ + qt * 128) * D_ + h * 64;
    const size_t vbase = (size_t)((b * 8 + h) * 64) * S_;

    {   // Q tile (hi/lo), 128 rows x 64 d, pitch 144B
        int r = tid >> 1, sg = (tid & 1) * 4;
        uint32_t d = sb + AQH + r * 144 + sg * 16;
        const size_t so = qrow + (size_t)r * D_ + sg * 8;
#pragma unroll
        for (int j = 0; j < 4; j++) {
            CP_ASYNC(d + j * 16,         g_q_hi + so + j * 8);
            CP_ASYNC(d + 18432 + j * 16, g_q_lo + so + j * 8);
        }
    }
    auto load_kv = [&](int t, int buf) {
        {
            int r = tid >> 1, sg = (tid & 1) * 4;
            uint32_t d = sb + AKH0 + buf * 36864 + r * 144 + sg * 16;
            const size_t so = (size_t)(b * S_ + t * 128 + r) * D_ + h * 64 + sg * 8;
#pragma unroll
            for (int j = 0; j < 4; j++) {
                CP_ASYNC(d + j * 16,         g_k_hi + so + j * 8);
                CP_ASYNC(d + 18432 + j * 16, g_k_lo + so + j * 8);
            }
        }
        {
            int r = tid >> 2, sg = (tid & 3) * 4;
            uint32_t d = sb + AVH0 + buf * 34816 + r * 272 + sg * 16;
            const size_t so = vbase + (size_t)r * S_ + t * 128 + sg * 8;
#pragma unroll
            for (int j = 0; j < 4; j++) {
                CP_ASYNC(d + j * 16,         g_vt_hi + so + j * 8);
                CP_ASYNC(d + 17408 + j * 16, g_vt_lo + so + j * 8);
            }
        }
    };
    load_kv(0, 0); CP_COMMIT();

    float o[8][4];
#pragma unroll
    for (int i = 0; i < 8; i++)
#pragma unroll
        for (int j = 0; j < 4; j++) o[i][j] = 0.f;
    float rs0 = 0.f, rs1 = 0.f;

    const uint32_t qarow = sb + AQH + (uint32_t)(w * 16 + (lane & 15)) * 144 + (lane >> 4) * 16;
    const uint32_t krow  = (uint32_t)(((lane >> 4) & 1) * 8 + (lane & 7)) * 144 + ((lane >> 3) & 1) * 16;
    const uint32_t vrow  = (uint32_t)(((lane >> 4) & 1) * 8 + (lane & 7)) * 272 + ((lane >> 3) & 1) * 16;
    const float CEXP = 0.18033688011112042f;   // log2(e)/8

    for (int t = 0; t < 16; t++) {
        if (t < 15) { load_kv(t + 1, (t + 1) & 1); CP_COMMIT(); CP_WAIT(1); }
        else CP_WAIT(0);
        __syncthreads();
        const uint32_t kb = sb + AKH0 + (t & 1) * 36864;
        const uint32_t vb = sb + AVH0 + (t & 1) * 34816;

        float s[16][4];
#pragma unroll
        for (int i = 0; i < 16; i++)
#pragma unroll
            for (int j = 0; j < 4; j++) s[i][j] = 0.f;

#pragma unroll
        for (int kk = 0; kk < 4; kk++) {
            uint32_t ah[4], al[4];
            ldsm4(ah, qarow + kk * 32);
            ldsm4(al, qarow + kk * 32 + 18432);
#pragma unroll
            for (int nt2 = 0; nt2 < 8; nt2++) {
                uint32_t ba = kb + krow + nt2 * 16 * 144 + kk * 32;
                uint32_t bh[4], bl[4];
                ldsm4(bh, ba);
                ldsm4(bl, ba + 18432);
                mma16816(s[nt2 * 2],     ah, &bh[0]);
                mma16816(s[nt2 * 2],     al, &bh[0]);
                mma16816(s[nt2 * 2],     ah, &bl[0]);
                mma16816(s[nt2 * 2 + 1], ah, &bh[2]);
                mma16816(s[nt2 * 2 + 1], al, &bh[2]);
                mma16816(s[nt2 * 2 + 1], ah, &bl[2]);
            }
        }

        // exp -> P split into hi/lo bf16 fragments (kills the 2^-9 P-rounding
        // term that caused rel_err 1.06e-3)
        uint32_t ph[32], pl[32];
#pragma unroll
        for (int nt = 0; nt < 16; nt++) {
            float e0 = fast_ex2(s[nt][0] * CEXP);
            float e1 = fast_ex2(s[nt][1] * CEXP);
            float e2 = fast_ex2(s[nt][2] * CEXP);
            float e3 = fast_ex2(s[nt][3] * CEXP);
            rs0 += e0 + e1;
            rs1 += e2 + e3;
            int kt = nt >> 1, hi2 = (nt & 1) * 2;
            split2(e0, e1, ph[kt * 4 + hi2],     pl[kt * 4 + hi2]);
            split2(e2, e3, ph[kt * 4 + hi2 + 1], pl[kt * 4 + hi2 + 1]);
        }

        // O += Ph@Vh + Pl@Vh + Ph@Vl (3-pass)
#pragma unroll
        for (int kt = 0; kt < 8; kt++) {
#pragma unroll
            for (int dt2 = 0; dt2 < 4; dt2++) {
                uint32_t va = vb + vrow + dt2 * 16 * 272 + kt * 32;
                uint32_t vh[4], vl[4];
                ldsm4(vh, va);
                ldsm4(vl, va + 17408);
                mma16816(o[dt2 * 2],     &ph[kt * 4], &vh[0]);
                mma16816(o[dt2 * 2],     &pl[kt * 4], &vh[0]);
                mma16816(o[dt2 * 2],     &ph[kt * 4], &vl[0]);
                mma16816(o[dt2 * 2 + 1], &ph[kt * 4], &vh[2]);
                mma16816(o[dt2 * 2 + 1], &pl[kt * 4], &vh[2]);
                mma16816(o[dt2 * 2 + 1], &ph[kt * 4], &vl[2]);
            }
        }
        __syncthreads();
    }

    rs0 += __shfl_xor_sync(0xffffffffu, rs0, 1);
    rs0 += __shfl_xor_sync(0xffffffffu, rs0, 2);
    rs1 += __shfl_xor_sync(0xffffffffu, rs1, 1);
    rs1 += __shfl_xor_sync(0xffffffffu, rs1, 2);
    const float i0 = 1.f / rs0, i1 = 1.f / rs1;

    size_t r0 = (size_t)(b * S_ + qt * 128 + w * 16 + (lane >> 2)) * D_ + h * 64 + 2 * (lane & 3);
#pragma unroll
    for (int dt = 0; dt < 8; dt++) {
        uint32_t uh, ul;
        split2(o[dt][0] * i0, o[dt][1] * i0, uh, ul);
        *reinterpret_cast<uint32_t*>(g_att_hi + r0 + dt * 8) = uh;
        *reinterpret_cast<uint32_t*>(g_att_lo + r0 + dt * 8) = ul;
        split2(o[dt][2] * i1, o[dt][3] * i1, uh, ul);
        *reinterpret_cast<uint32_t*>(g_att_hi + r0 + 8 * D_ + dt * 8) = uh;
        *reinterpret_cast<uint32_t*>(g_att_lo + r0 + 8 * D_ + dt * 8) = ul;
    }
}

// ------------------------- launch -----------------------------------------
extern "C" void kernel_launch(void* const* d_in, const int* in_sizes, int n_in,
                              void* d_out, int out_size) {
    const float* x  = (const float*)d_in[0];
    const float* Wq = (const float*)d_in[1];
    const float* Wk = (const float*)d_in[2];
    const float* Wv = (const float*)d_in[3];
    const float* Wo = (const float*)d_in[4];
    const float* bo = (const float*)d_in[5];
    float* out = (float*)d_out;

    cudaFuncSetAttribute(gemm_mma, cudaFuncAttributeMaxDynamicSharedMemorySize, GSM);
    cudaFuncSetAttribute(attn_mma, cudaFuncAttributeMaxDynamicSharedMemorySize, ASMB);

    cvt_x<<<(TOK * D_) / 1024, 256>>>(x);
    cvt_w<<<dim3(16, 16, 4), 256>>>(Wq, Wk, Wv, Wo);
    gemm_mma<<<dim3(TOK / 128, D_ / 128, 3), 256, GSM>>>(0, nullptr, nullptr);  // Q,K,V
    attn_mma<<<dim3(S_ / 128, B_ * 8), 256, ASMB>>>();
    gemm_mma<<<dim3(TOK / 128, D_ / 128, 1), 256, GSM>>>(3, bo, out);           // O-proj
}

// round 11
// speedup vs baseline: 2.7745x; 1.1860x over previous
#include <cuda_runtime.h>
#include <cuda_bf16.h>
#include <cstdint>

#define B_ 4
#define S_ 2048
#define D_ 512
#define TOK (B_*S_)
#define SCALE_ 0.125f

// ------------------------- device scratch ---------------------------------
__device__ __nv_bfloat16 g_x_hi[TOK*D_],  g_x_lo[TOK*D_];
__device__ __nv_bfloat16 g_wt_hi[4*D_*D_], g_wt_lo[4*D_*D_];   // [n][k]
__device__ __nv_bfloat16 g_q_hi[TOK*D_],  g_q_lo[TOK*D_];
__device__ __nv_bfloat16 g_k_hi[TOK*D_],  g_k_lo[TOK*D_];
__device__ __nv_bfloat16 g_vt_hi[TOK*D_], g_vt_lo[TOK*D_];     // [b,h,d,S]
__device__ __nv_bfloat16 g_att_hi[TOK*D_], g_att_lo[TOK*D_];

// ------------------------- PTX helpers ------------------------------------
__device__ __forceinline__ uint32_t smem_u32(const void* p) {
    uint32_t a;
    asm("{ .reg .u64 t; cvta.to.shared.u64 t, %1; cvt.u32.u64 %0, t; }"
        : "=r"(a) : "l"(p));
    return a;
}
#define CP_ASYNC(d, s) asm volatile("cp.async.cg.shared.global [%0], [%1], 16;" :: "r"(d), "l"(s) : "memory")
#define CP_COMMIT()    asm volatile("cp.async.commit_group;" ::: "memory")
#define CP_WAIT(n)     asm volatile("cp.async.wait_group %0;" :: "n"(n) : "memory")

__device__ __forceinline__ void ldsm4(uint32_t* r, uint32_t a) {
    asm volatile("ldmatrix.sync.aligned.m8n8.x4.shared.b16 {%0,%1,%2,%3}, [%4];"
        : "=r"(r[0]), "=r"(r[1]), "=r"(r[2]), "=r"(r[3]) : "r"(a));
}
__device__ __forceinline__ void mma16816(float* c, const uint32_t* a, const uint32_t* b) {
    asm volatile("mma.sync.aligned.m16n8k16.row.col.f32.bf16.bf16.f32 "
        "{%0,%1,%2,%3}, {%4,%5,%6,%7}, {%8,%9}, {%0,%1,%2,%3};"
        : "+f"(c[0]), "+f"(c[1]), "+f"(c[2]), "+f"(c[3])
        : "r"(a[0]), "r"(a[1]), "r"(a[2]), "r"(a[3]), "r"(b[0]), "r"(b[1]));
}
__device__ __forceinline__ float fast_ex2(float x) {
    float y; asm("ex2.approx.f32 %0, %1;" : "=f"(y) : "f"(x)); return y;
}
__device__ __forceinline__ void split2(float f0, float f1, uint32_t& h, uint32_t& l) {
    __nv_bfloat16 h0 = __float2bfloat16(f0), h1 = __float2bfloat16(f1);
    __nv_bfloat16 l0 = __float2bfloat16(f0 - __bfloat162float(h0));
    __nv_bfloat16 l1 = __float2bfloat16(f1 - __bfloat162float(h1));
    __nv_bfloat162 th = __halves2bfloat162(h0, h1), tl = __halves2bfloat162(l0, l1);
    h = *reinterpret_cast<uint32_t*>(&th);
    l = *reinterpret_cast<uint32_t*>(&tl);
}
// 64 strided floats -> 64 bf16 hi + 64 bf16 lo (vectorized 16B stores)
__device__ __forceinline__ void row64_hi_lo(const float* src, int stride,
                                            __nv_bfloat16* oh, __nv_bfloat16* ol) {
#pragma unroll
    for (int g = 0; g < 8; g++) {
        uint32_t hh[4], ll[4];
#pragma unroll
        for (int p = 0; p < 4; p++)
            split2(src[(g*8 + p*2) * stride], src[(g*8 + p*2 + 1) * stride], hh[p], ll[p]);
        *reinterpret_cast<uint4*>(oh + g*8) = make_uint4(hh[0], hh[1], hh[2], hh[3]);
        *reinterpret_cast<uint4*>(ol + g*8) = make_uint4(ll[0], ll[1], ll[2], ll[3]);
    }
}

// ------------------------- prep kernels -----------------------------------
__global__ __launch_bounds__(256) void cvt_x(const float* __restrict__ x) {
    size_t i = ((size_t)blockIdx.x * 256 + threadIdx.x) * 4;
    float4 v = *reinterpret_cast<const float4*>(x + i);
    uint32_t h0, l0, h1, l1;
    split2(v.x, v.y, h0, l0);
    split2(v.z, v.w, h1, l1);
    *reinterpret_cast<uint2*>(g_x_hi + i) = make_uint2(h0, h1);
    *reinterpret_cast<uint2*>(g_x_lo + i) = make_uint2(l0, l1);
}

__global__ __launch_bounds__(256) void cvt_w(const float* __restrict__ Wq,
                                             const float* __restrict__ Wk,
                                             const float* __restrict__ Wv,
                                             const float* __restrict__ Wo) {
    __shared__ float t[32][33];
    const int z = blockIdx.z;
    const float* W = (z == 0) ? Wq : (z == 1) ? Wk : (z == 2) ? Wv : Wo;
    const int k0 = blockIdx.x * 32, n0 = blockIdx.y * 32;
    const int tx = threadIdx.x & 31, ty = threadIdx.x >> 5;
#pragma unroll
    for (int r = 0; r < 4; r++)
        t[ty + r * 8][tx] = W[(size_t)(k0 + ty + r * 8) * D_ + n0 + tx];
    __syncthreads();
#pragma unroll
    for (int r = 0; r < 4; r++) {
        int nn = ty + r * 8;
        float f = t[tx][nn];
        __nv_bfloat16 h = __float2bfloat16(f);
        size_t oi = (size_t)z * D_ * D_ + (size_t)(n0 + nn) * D_ + k0 + tx;
        g_wt_hi[oi] = h;
        g_wt_lo[oi] = __float2bfloat16(f - __bfloat162float(h));
    }
}

// ------------------------- HMMA GEMM --------------------------------------
// C[8192,512] = A @ W, block 128x128, warp 64x32, k-chunks of 32, split-bf16
// 3-pass. smem: per buf {Ah,Al,Bh,Bl} 128x(80B pitch). modes: 0=Q 1=K 2=V(T) 3=O
#define GSM 81920

__global__ __launch_bounds__(256, 2) void gemm_mma(int mode_base,
                                                   const float* __restrict__ bias,
                                                   float* __restrict__ out) {
    extern __shared__ char sm[];
    const int tid = threadIdx.x, lane = tid & 31, w = tid >> 5;
    const int wm = w & 1, wn = w >> 1;
    const int mode = mode_base + blockIdx.z;
    const int m0 = blockIdx.x * 128, n0 = blockIdx.y * 128;
    const uint32_t sb = smem_u32(sm);

    const __nv_bfloat16* Ah = ((mode < 3) ? g_x_hi : g_att_hi) + (size_t)m0 * D_;
    const __nv_bfloat16* Al = ((mode < 3) ? g_x_lo : g_att_lo) + (size_t)m0 * D_;
    const __nv_bfloat16* Bh = g_wt_hi + (size_t)mode * D_ * D_ + (size_t)n0 * D_;
    const __nv_bfloat16* Bl = g_wt_lo + (size_t)mode * D_ * D_ + (size_t)n0 * D_;

    float acc[4][4][4];
#pragma unroll
    for (int i = 0; i < 4; i++)
#pragma unroll
        for (int j = 0; j < 4; j++)
#pragma unroll
            for (int k = 0; k < 4; k++) acc[i][j][k] = 0.f;

    const int lr = tid >> 1, sgb = (tid & 1) * 2;
    auto load_chunk = [&](int buf, int k0) {
        uint32_t d = sb + buf * 40960 + lr * 80 + sgb * 16;
        const size_t so = (size_t)lr * D_ + k0 + sgb * 8;
#pragma unroll
        for (int j = 0; j < 2; j++) {
            CP_ASYNC(d + j * 16,         Ah + so + j * 8);
            CP_ASYNC(d + 10240 + j * 16, Al + so + j * 8);
            CP_ASYNC(d + 20480 + j * 16, Bh + so + j * 8);
            CP_ASYNC(d + 30720 + j * 16, Bl + so + j * 8);
        }
    };

    load_chunk(0, 0); CP_COMMIT();
    const uint32_t arow = (uint32_t)(wm * 64 + (lane & 15)) * 80 + (lane >> 4) * 16;
    const uint32_t brow = (uint32_t)(wn * 32 + ((lane >> 4) & 1) * 8 + (lane & 7)) * 80
                          + ((lane >> 3) & 1) * 16;

    for (int c = 0; c < 16; c++) {
        if (c < 15) { load_chunk((c + 1) & 1, (c + 1) * 32); CP_COMMIT(); CP_WAIT(1); }
        else CP_WAIT(0);
        __syncthreads();
        const uint32_t base = sb + (c & 1) * 40960;
#pragma unroll
        for (int kk = 0; kk < 2; kk++) {
            uint32_t bh[2][4], bl[2][4];
#pragma unroll
            for (int nt2 = 0; nt2 < 2; nt2++) {
                uint32_t ba = base + 20480 + brow + nt2 * 16 * 80 + kk * 32;
                ldsm4(bh[nt2], ba);
                ldsm4(bl[nt2], ba + 10240);
            }
#pragma unroll
            for (int mt = 0; mt < 4; mt++) {
                uint32_t aa = base + arow + mt * 16 * 80 + kk * 32;
                uint32_t ah[4], al[4];
                ldsm4(ah, aa);
                ldsm4(al, aa + 10240);
#pragma unroll
                for (int nt2 = 0; nt2 < 2; nt2++) {
                    mma16816(acc[mt][nt2 * 2],     ah, &bh[nt2][0]);
                    mma16816(acc[mt][nt2 * 2],     al, &bh[nt2][0]);
                    mma16816(acc[mt][nt2 * 2],     ah, &bl[nt2][0]);
                    mma16816(acc[mt][nt2 * 2 + 1], ah, &bh[nt2][2]);
                    mma16816(acc[mt][nt2 * 2 + 1], al, &bh[nt2][2]);
                    mma16816(acc[mt][nt2 * 2 + 1], ah, &bl[nt2][2]);
                }
            }
        }
        __syncthreads();
    }

    // stage C into smem [128][132] f32, then mode-specific vectorized writes
    float* cs = reinterpret_cast<float*>(sm);
    {
        const int rr = wm * 64 + (lane >> 2), cc = wn * 32 + 2 * (lane & 3);
#pragma unroll
        for (int mt = 0; mt < 4; mt++)
#pragma unroll
            for (int nt = 0; nt < 4; nt++) {
                int r0 = rr + mt * 16, c0 = cc + nt * 8;
                cs[r0 * 132 + c0]           = acc[mt][nt][0];
                cs[r0 * 132 + c0 + 1]       = acc[mt][nt][1];
                cs[(r0 + 8) * 132 + c0]     = acc[mt][nt][2];
                cs[(r0 + 8) * 132 + c0 + 1] = acc[mt][nt][3];
            }
    }
    __syncthreads();

    if (mode <= 1) {
        int r = tid >> 1, hf = tid & 1;
        size_t ob = (size_t)(m0 + r) * D_ + n0 + hf * 64;
        row64_hi_lo(cs + r * 132 + hf * 64, 1,
                    (mode ? g_k_hi : g_q_hi) + ob, (mode ? g_k_lo : g_q_lo) + ob);
    } else if (mode == 3) {
        int r = tid >> 1, hf = tid & 1;
        float* op = out + (size_t)(m0 + r) * D_ + n0 + hf * 64;
        const float* sp = cs + r * 132 + hf * 64;
        const float* bp = bias + n0 + hf * 64;
#pragma unroll
        for (int g = 0; g < 16; g++) {
            float4 v;
            v.x = sp[g * 4 + 0] + bp[g * 4 + 0];
            v.y = sp[g * 4 + 1] + bp[g * 4 + 1];
            v.z = sp[g * 4 + 2] + bp[g * 4 + 2];
            v.w = sp[g * 4 + 3] + bp[g * 4 + 3];
            *reinterpret_cast<float4*>(op + g * 4) = v;
        }
    } else {   // V: transpose -> [b,h,d,S]
        int dl = tid >> 1, sh = tid & 1;
        int dg = n0 + dl, hh = dg >> 6, dd = dg & 63, bb = m0 >> 11;
        size_t ob = ((size_t)(bb * 8 + hh) * 64 + dd) * (size_t)S_ + (m0 & 2047) + sh * 64;
        row64_hi_lo(cs + (sh * 64) * 132 + dl, 132, g_vt_hi + ob, g_vt_lo + ob);
    }
}

// ------------------------- attention --------------------------------------
// CTA = 128 q-rows x (b,h); 2 CTAs/SM (smem 108KB, regs <=128).
// kv tiles of 64, double-buffered K+V. Q fragments register-resident.
// S frags -> per-16kv streamed exp/split -> 3-pass PV. Unnormalized O accum.
#define AQ  0        /* Q hi; lo at +18432; 36864 total */
#define AK  36864    /* + buf*18432; lo at +9216 */
#define AV  73728    /* + buf*18432; lo at +9216 */
#define ASMB 110592

__global__ __launch_bounds__(256, 2) void attn_mma() {
    extern __shared__ char sm[];
    const int tid = threadIdx.x, lane = tid & 31, w = tid >> 5;
    const int qt = blockIdx.x, b = blockIdx.y >> 3, h = blockIdx.y & 7;
    const uint32_t sb = smem_u32(sm);

    const size_t qbase = (size_t)(b * S_ + qt * 128) * D_ + h * 64;
    const size_t vbase = (size_t)((b * 8 + h) * 64) * S_;

    {   // Q tile (hi/lo), 128 rows x 64 d, pitch 144B
        int r = tid >> 1, sg = (tid & 1) * 4;
        uint32_t d = sb + AQ + r * 144 + sg * 16;
        const size_t so = qbase + (size_t)r * D_ + sg * 8;
#pragma unroll
        for (int j = 0; j < 4; j++) {
            CP_ASYNC(d + j * 16,         g_q_hi + so + j * 8);
            CP_ASYNC(d + 18432 + j * 16, g_q_lo + so + j * 8);
        }
    }
    auto load_kv = [&](int t, int buf) {
        int r = tid >> 2, sg = (tid & 3) * 2;
        {   // K: 64 rows x 64 d
            uint32_t d = sb + AK + buf * 18432 + r * 144 + sg * 16;
            const size_t so = (size_t)(b * S_ + t * 64 + r) * D_ + h * 64 + sg * 8;
#pragma unroll
            for (int j = 0; j < 2; j++) {
                CP_ASYNC(d + j * 16,        g_k_hi + so + j * 8);
                CP_ASYNC(d + 9216 + j * 16, g_k_lo + so + j * 8);
            }
        }
        {   // V: 64 d rows x 64 kv cols (from [d][S])
            uint32_t d = sb + AV + buf * 18432 + r * 144 + sg * 16;
            const size_t so = vbase + (size_t)r * S_ + t * 64 + sg * 8;
#pragma unroll
            for (int j = 0; j < 2; j++) {
                CP_ASYNC(d + j * 16,        g_vt_hi + so + j * 8);
                CP_ASYNC(d + 9216 + j * 16, g_vt_lo + so + j * 8);
            }
        }
    };
    load_kv(0, 0); CP_COMMIT();

    // wait for Q + tile0, then make Q fragments register-resident
    CP_WAIT(0);
    __syncthreads();
    const uint32_t qarow = sb + AQ + (uint32_t)(w * 16 + (lane & 15)) * 144 + (lane >> 4) * 16;
    uint32_t qh[4][4], ql[4][4];
#pragma unroll
    for (int kk = 0; kk < 4; kk++) {
        ldsm4(qh[kk], qarow + kk * 32);
        ldsm4(ql[kk], qarow + kk * 32 + 18432);
    }

    float o[8][4];
#pragma unroll
    for (int i = 0; i < 8; i++)
#pragma unroll
        for (int j = 0; j < 4; j++) o[i][j] = 0.f;
    float rs0 = 0.f, rs1 = 0.f;

    const uint32_t krow = (uint32_t)(((lane >> 4) & 1) * 8 + (lane & 7)) * 144 + ((lane >> 3) & 1) * 16;
    const float CEXP = 0.18033688011112042f;   // log2(e)/8

    for (int t = 0; t < 32; t++) {
        if (t < 31) { load_kv(t + 1, (t + 1) & 1); CP_COMMIT(); CP_WAIT(1); }
        else CP_WAIT(0);
        __syncthreads();
        const uint32_t kb = sb + AK + (t & 1) * 18432;
        const uint32_t vb = sb + AV + (t & 1) * 18432;

        // S = Q @ K^T (3-pass split), 16 q-rows x 64 kv
        float s[8][4];
#pragma unroll
        for (int i = 0; i < 8; i++)
#pragma unroll
            for (int j = 0; j < 4; j++) s[i][j] = 0.f;

#pragma unroll
        for (int kk = 0; kk < 4; kk++) {
#pragma unroll
            for (int nt2 = 0; nt2 < 4; nt2++) {
                uint32_t ba = kb + krow + nt2 * 16 * 144 + kk * 32;
                uint32_t bh[4], bl[4];
                ldsm4(bh, ba);
                ldsm4(bl, ba + 9216);
                mma16816(s[nt2 * 2],     qh[kk], &bh[0]);
                mma16816(s[nt2 * 2],     ql[kk], &bh[0]);
                mma16816(s[nt2 * 2],     qh[kk], &bl[0]);
                mma16816(s[nt2 * 2 + 1], qh[kk], &bh[2]);
                mma16816(s[nt2 * 2 + 1], ql[kk], &bh[2]);
                mma16816(s[nt2 * 2 + 1], qh[kk], &bl[2]);
            }
        }

        // per 16-kv chunk: exp -> P hi/lo frag -> 3-pass PV (streams s away)
#pragma unroll
        for (int kt = 0; kt < 4; kt++) {
            float e0 = fast_ex2(s[2*kt][0] * CEXP),   e1 = fast_ex2(s[2*kt][1] * CEXP);
            float e2 = fast_ex2(s[2*kt][2] * CEXP),   e3 = fast_ex2(s[2*kt][3] * CEXP);
            float e4 = fast_ex2(s[2*kt+1][0] * CEXP), e5 = fast_ex2(s[2*kt+1][1] * CEXP);
            float e6 = fast_ex2(s[2*kt+1][2] * CEXP), e7 = fast_ex2(s[2*kt+1][3] * CEXP);
            rs0 += e0 + e1 + e4 + e5;
            rs1 += e2 + e3 + e6 + e7;
            uint32_t ph[4], pl[4];
            split2(e0, e1, ph[0], pl[0]);
            split2(e2, e3, ph[1], pl[1]);
            split2(e4, e5, ph[2], pl[2]);
            split2(e6, e7, ph[3], pl[3]);
#pragma unroll
            for (int dt2 = 0; dt2 < 4; dt2++) {
                uint32_t va = vb + krow + dt2 * 16 * 144 + kt * 32;
                uint32_t vh[4], vl[4];
                ldsm4(vh, va);
                ldsm4(vl, va + 9216);
                mma16816(o[dt2 * 2],     ph, &vh[0]);
                mma16816(o[dt2 * 2],     pl, &vh[0]);
                mma16816(o[dt2 * 2],     ph, &vl[0]);
                mma16816(o[dt2 * 2 + 1], ph, &vh[2]);
                mma16816(o[dt2 * 2 + 1], pl, &vh[2]);
                mma16816(o[dt2 * 2 + 1], ph, &vl[2]);
            }
        }
        __syncthreads();
    }

    rs0 += __shfl_xor_sync(0xffffffffu, rs0, 1);
    rs0 += __shfl_xor_sync(0xffffffffu, rs0, 2);
    rs1 += __shfl_xor_sync(0xffffffffu, rs1, 1);
    rs1 += __shfl_xor_sync(0xffffffffu, rs1, 2);
    const float i0 = 1.f / rs0, i1 = 1.f / rs1;

    size_t r0 = (size_t)(b * S_ + qt * 128 + w * 16 + (lane >> 2)) * D_ + h * 64 + 2 * (lane & 3);
#pragma unroll
    for (int dt = 0; dt < 8; dt++) {
        uint32_t uh, ul;
        split2(o[dt][0] * i0, o[dt][1] * i0, uh, ul);
        *reinterpret_cast<uint32_t*>(g_att_hi + r0 + dt * 8) = uh;
        *reinterpret_cast<uint32_t*>(g_att_lo + r0 + dt * 8) = ul;
        split2(o[dt][2] * i1, o[dt][3] * i1, uh, ul);
        *reinterpret_cast<uint32_t*>(g_att_hi + r0 + 8 * D_ + dt * 8) = uh;
        *reinterpret_cast<uint32_t*>(g_att_lo + r0 + 8 * D_ + dt * 8) = ul;
    }
}

// ------------------------- launch -----------------------------------------
extern "C" void kernel_launch(void* const* d_in, const int* in_sizes, int n_in,
                              void* d_out, int out_size) {
    const float* x  = (const float*)d_in[0];
    const float* Wq = (const float*)d_in[1];
    const float* Wk = (const float*)d_in[2];
    const float* Wv = (const float*)d_in[3];
    const float* Wo = (const float*)d_in[4];
    const float* bo = (const float*)d_in[5];
    float* out = (float*)d_out;

    cudaFuncSetAttribute(gemm_mma, cudaFuncAttributeMaxDynamicSharedMemorySize, GSM);
    cudaFuncSetAttribute(attn_mma, cudaFuncAttributeMaxDynamicSharedMemorySize, ASMB);

    cvt_x<<<(TOK * D_) / 1024, 256>>>(x);
    cvt_w<<<dim3(16, 16, 4), 256>>>(Wq, Wk, Wv, Wo);
    gemm_mma<<<dim3(TOK / 128, D_ / 128, 3), 256, GSM>>>(0, nullptr, nullptr);  // Q,K,V
    attn_mma<<<dim3(S_ / 128, B_ * 8), 256, ASMB>>>();
    gemm_mma<<<dim3(TOK / 128, D_ / 128, 1), 256, GSM>>>(3, bo, out);           // O-proj
}

// round 12
// speedup vs baseline: 4.0239x; 1.4503x over previous
#include <cuda_runtime.h>
#include <cuda_bf16.h>
#include <cuda_fp16.h>
#include <cstdint>

#define B_ 4
#define S_ 2048
#define D_ 512
#define TOK (B_*S_)

// ------------------------- device scratch ---------------------------------
__device__ __nv_bfloat16 g_x_hi[TOK*D_],  g_x_lo[TOK*D_];
__device__ __nv_bfloat16 g_wt_hi[4*D_*D_], g_wt_lo[4*D_*D_];   // [n][k]
__device__ __half g_q_fh[TOK*D_], g_q_fl[TOK*D_];   // Q fp16 hi/lo
__device__ __half g_k_f[TOK*D_];                    // K fp16 single
__device__ __half g_vt_f[TOK*D_];                   // V fp16 single, [b,h,d,S]
__device__ __nv_bfloat16 g_att_hi[TOK*D_], g_att_lo[TOK*D_];

// ------------------------- PTX helpers ------------------------------------
__device__ __forceinline__ uint32_t smem_u32(const void* p) {
    uint32_t a;
    asm("{ .reg .u64 t; cvta.to.shared.u64 t, %1; cvt.u32.u64 %0, t; }"
        : "=r"(a) : "l"(p));
    return a;
}
#define CP_ASYNC(d, s) asm volatile("cp.async.cg.shared.global [%0], [%1], 16;" :: "r"(d), "l"(s) : "memory")
#define CP_COMMIT()    asm volatile("cp.async.commit_group;" ::: "memory")
#define CP_WAIT(n)     asm volatile("cp.async.wait_group %0;" :: "n"(n) : "memory")

__device__ __forceinline__ void ldsm4(uint32_t* r, uint32_t a) {
    asm volatile("ldmatrix.sync.aligned.m8n8.x4.shared.b16 {%0,%1,%2,%3}, [%4];"
        : "=r"(r[0]), "=r"(r[1]), "=r"(r[2]), "=r"(r[3]) : "r"(a));
}
__device__ __forceinline__ void mma16816(float* c, const uint32_t* a, const uint32_t* b) {
    asm volatile("mma.sync.aligned.m16n8k16.row.col.f32.bf16.bf16.f32 "
        "{%0,%1,%2,%3}, {%4,%5,%6,%7}, {%8,%9}, {%0,%1,%2,%3};"
        : "+f"(c[0]), "+f"(c[1]), "+f"(c[2]), "+f"(c[3])
        : "r"(a[0]), "r"(a[1]), "r"(a[2]), "r"(a[3]), "r"(b[0]), "r"(b[1]));
}
__device__ __forceinline__ void mma16816h(float* c, const uint32_t* a, const uint32_t* b) {
    asm volatile("mma.sync.aligned.m16n8k16.row.col.f32.f16.f16.f32 "
        "{%0,%1,%2,%3}, {%4,%5,%6,%7}, {%8,%9}, {%0,%1,%2,%3};"
        : "+f"(c[0]), "+f"(c[1]), "+f"(c[2]), "+f"(c[3])
        : "r"(a[0]), "r"(a[1]), "r"(a[2]), "r"(a[3]), "r"(b[0]), "r"(b[1]));
}
__device__ __forceinline__ float fast_ex2(float x) {
    float y; asm("ex2.approx.f32 %0, %1;" : "=f"(y) : "f"(x)); return y;
}
// bf16 split (for GEMM path + att output)
__device__ __forceinline__ void split2(float f0, float f1, uint32_t& h, uint32_t& l) {
    __nv_bfloat16 h0 = __float2bfloat16(f0), h1 = __float2bfloat16(f1);
    __nv_bfloat16 l0 = __float2bfloat16(f0 - __bfloat162float(h0));
    __nv_bfloat16 l1 = __float2bfloat16(f1 - __bfloat162float(h1));
    __nv_bfloat162 th = __halves2bfloat162(h0, h1), tl = __halves2bfloat162(l0, l1);
    h = *reinterpret_cast<uint32_t*>(&th);
    l = *reinterpret_cast<uint32_t*>(&tl);
}
// fp16 split
__device__ __forceinline__ void split2h(float f0, float f1, uint32_t& h, uint32_t& l) {
    __half h0 = __float2half_rn(f0), h1 = __float2half_rn(f1);
    __half l0 = __float2half_rn(f0 - __half2float(h0));
    __half l1 = __float2half_rn(f1 - __half2float(h1));
    __half2 th = __halves2half2(h0, h1), tl = __halves2half2(l0, l1);
    h = *reinterpret_cast<uint32_t*>(&th);
    l = *reinterpret_cast<uint32_t*>(&tl);
}
__device__ __forceinline__ uint32_t pack2h(float x, float y) {
    __half2 t = __floats2half2_rn(x, y);
    return *reinterpret_cast<uint32_t*>(&t);
}
// 64 strided floats -> 64 bf16 hi + lo
__device__ __forceinline__ void row64_hi_lo(const float* src, int stride,
                                            __nv_bfloat16* oh, __nv_bfloat16* ol) {
#pragma unroll
    for (int g = 0; g < 8; g++) {
        uint32_t hh[4], ll[4];
#pragma unroll
        for (int p = 0; p < 4; p++)
            split2(src[(g*8 + p*2) * stride], src[(g*8 + p*2 + 1) * stride], hh[p], ll[p]);
        *reinterpret_cast<uint4*>(oh + g*8) = make_uint4(hh[0], hh[1], hh[2], hh[3]);
        *reinterpret_cast<uint4*>(ol + g*8) = make_uint4(ll[0], ll[1], ll[2], ll[3]);
    }
}
// 64 strided floats -> 64 fp16 hi + lo
__device__ __forceinline__ void row64_h_split(const float* src, int stride,
                                              __half* oh, __half* ol) {
#pragma unroll
    for (int g = 0; g < 8; g++) {
        uint32_t hh[4], ll[4];
#pragma unroll
        for (int p = 0; p < 4; p++)
            split2h(src[(g*8 + p*2) * stride], src[(g*8 + p*2 + 1) * stride], hh[p], ll[p]);
        *reinterpret_cast<uint4*>(oh + g*8) = make_uint4(hh[0], hh[1], hh[2], hh[3]);
        *reinterpret_cast<uint4*>(ol + g*8) = make_uint4(ll[0], ll[1], ll[2], ll[3]);
    }
}
// 64 strided floats -> 64 fp16 single
__device__ __forceinline__ void row64_h(const float* src, int stride, __half* o) {
#pragma unroll
    for (int g = 0; g < 8; g++) {
        uint32_t hh[4];
#pragma unroll
        for (int p = 0; p < 4; p++)
            hh[p] = pack2h(src[(g*8 + p*2) * stride], src[(g*8 + p*2 + 1) * stride]);
        *reinterpret_cast<uint4*>(o + g*8) = make_uint4(hh[0], hh[1], hh[2], hh[3]);
    }
}

// ------------------------- prep kernels -----------------------------------
__global__ __launch_bounds__(256) void cvt_x(const float* __restrict__ x) {
    size_t i = ((size_t)blockIdx.x * 256 + threadIdx.x) * 4;
    float4 v = *reinterpret_cast<const float4*>(x + i);
    uint32_t h0, l0, h1, l1;
    split2(v.x, v.y, h0, l0);
    split2(v.z, v.w, h1, l1);
    *reinterpret_cast<uint2*>(g_x_hi + i) = make_uint2(h0, h1);
    *reinterpret_cast<uint2*>(g_x_lo + i) = make_uint2(l0, l1);
}

__global__ __launch_bounds__(256) void cvt_w(const float* __restrict__ Wq,
                                             const float* __restrict__ Wk,
                                             const float* __restrict__ Wv,
                                             const float* __restrict__ Wo) {
    __shared__ float t[32][33];
    const int z = blockIdx.z;
    const float* W = (z == 0) ? Wq : (z == 1) ? Wk : (z == 2) ? Wv : Wo;
    const int k0 = blockIdx.x * 32, n0 = blockIdx.y * 32;
    const int tx = threadIdx.x & 31, ty = threadIdx.x >> 5;
#pragma unroll
    for (int r = 0; r < 4; r++)
        t[ty + r * 8][tx] = W[(size_t)(k0 + ty + r * 8) * D_ + n0 + tx];
    __syncthreads();
#pragma unroll
    for (int r = 0; r < 4; r++) {
        int nn = ty + r * 8;
        float f = t[tx][nn];
        __nv_bfloat16 h = __float2bfloat16(f);
        size_t oi = (size_t)z * D_ * D_ + (size_t)(n0 + nn) * D_ + k0 + tx;
        g_wt_hi[oi] = h;
        g_wt_lo[oi] = __float2bfloat16(f - __bfloat162float(h));
    }
}

// ------------------------- HMMA GEMM (bf16 3-pass) -------------------------
// modes: 0=Q(fp16 split out) 1=K(fp16 single) 2=V(fp16 single, transposed) 3=O
#define GSM 81920

__global__ __launch_bounds__(256, 2) void gemm_mma(int mode_base,
                                                   const float* __restrict__ bias,
                                                   float* __restrict__ out) {
    extern __shared__ char sm[];
    const int tid = threadIdx.x, lane = tid & 31, w = tid >> 5;
    const int wm = w & 1, wn = w >> 1;
    const int mode = mode_base + blockIdx.z;
    const int m0 = blockIdx.x * 128, n0 = blockIdx.y * 128;
    const uint32_t sb = smem_u32(sm);

    const __nv_bfloat16* Ah = ((mode < 3) ? g_x_hi : g_att_hi) + (size_t)m0 * D_;
    const __nv_bfloat16* Al = ((mode < 3) ? g_x_lo : g_att_lo) + (size_t)m0 * D_;
    const __nv_bfloat16* Bh = g_wt_hi + (size_t)mode * D_ * D_ + (size_t)n0 * D_;
    const __nv_bfloat16* Bl = g_wt_lo + (size_t)mode * D_ * D_ + (size_t)n0 * D_;

    float acc[4][4][4];
#pragma unroll
    for (int i = 0; i < 4; i++)
#pragma unroll
        for (int j = 0; j < 4; j++)
#pragma unroll
            for (int k = 0; k < 4; k++) acc[i][j][k] = 0.f;

    const int lr = tid >> 1, sgb = (tid & 1) * 2;
    auto load_chunk = [&](int buf, int k0) {
        uint32_t d = sb + buf * 40960 + lr * 80 + sgb * 16;
        const size_t so = (size_t)lr * D_ + k0 + sgb * 8;
#pragma unroll
        for (int j = 0; j < 2; j++) {
            CP_ASYNC(d + j * 16,         Ah + so + j * 8);
            CP_ASYNC(d + 10240 + j * 16, Al + so + j * 8);
            CP_ASYNC(d + 20480 + j * 16, Bh + so + j * 8);
            CP_ASYNC(d + 30720 + j * 16, Bl + so + j * 8);
        }
    };

    load_chunk(0, 0); CP_COMMIT();
    const uint32_t arow = (uint32_t)(wm * 64 + (lane & 15)) * 80 + (lane >> 4) * 16;
    const uint32_t brow = (uint32_t)(wn * 32 + ((lane >> 4) & 1) * 8 + (lane & 7)) * 80
                          + ((lane >> 3) & 1) * 16;

    for (int c = 0; c < 16; c++) {
        if (c < 15) { load_chunk((c + 1) & 1, (c + 1) * 32); CP_COMMIT(); CP_WAIT(1); }
        else CP_WAIT(0);
        __syncthreads();
        const uint32_t base = sb + (c & 1) * 40960;
#pragma unroll
        for (int kk = 0; kk < 2; kk++) {
            uint32_t bh[2][4], bl[2][4];
#pragma unroll
            for (int nt2 = 0; nt2 < 2; nt2++) {
                uint32_t ba = base + 20480 + brow + nt2 * 16 * 80 + kk * 32;
                ldsm4(bh[nt2], ba);
                ldsm4(bl[nt2], ba + 10240);
            }
#pragma unroll
            for (int mt = 0; mt < 4; mt++) {
                uint32_t aa = base + arow + mt * 16 * 80 + kk * 32;
                uint32_t ah[4], al[4];
                ldsm4(ah, aa);
                ldsm4(al, aa + 10240);
#pragma unroll
                for (int nt2 = 0; nt2 < 2; nt2++) {
                    mma16816(acc[mt][nt2 * 2],     ah, &bh[nt2][0]);
                    mma16816(acc[mt][nt2 * 2],     al, &bh[nt2][0]);
                    mma16816(acc[mt][nt2 * 2],     ah, &bl[nt2][0]);
                    mma16816(acc[mt][nt2 * 2 + 1], ah, &bh[nt2][2]);
                    mma16816(acc[mt][nt2 * 2 + 1], al, &bh[nt2][2]);
                    mma16816(acc[mt][nt2 * 2 + 1], ah, &bl[nt2][2]);
                }
            }
        }
        __syncthreads();
    }

    // stage C into smem [128][132] f32
    float* cs = reinterpret_cast<float*>(sm);
    {
        const int rr = wm * 64 + (lane >> 2), cc = wn * 32 + 2 * (lane & 3);
#pragma unroll
        for (int mt = 0; mt < 4; mt++)
#pragma unroll
            for (int nt = 0; nt < 4; nt++) {
                int r0 = rr + mt * 16, c0 = cc + nt * 8;
                cs[r0 * 132 + c0]           = acc[mt][nt][0];
                cs[r0 * 132 + c0 + 1]       = acc[mt][nt][1];
                cs[(r0 + 8) * 132 + c0]     = acc[mt][nt][2];
                cs[(r0 + 8) * 132 + c0 + 1] = acc[mt][nt][3];
            }
    }
    __syncthreads();

    if (mode == 0) {        // Q -> fp16 hi/lo
        int r = tid >> 1, hf = tid & 1;
        size_t ob = (size_t)(m0 + r) * D_ + n0 + hf * 64;
        row64_h_split(cs + r * 132 + hf * 64, 1, g_q_fh + ob, g_q_fl + ob);
    } else if (mode == 1) { // K -> fp16 single
        int r = tid >> 1, hf = tid & 1;
        size_t ob = (size_t)(m0 + r) * D_ + n0 + hf * 64;
        row64_h(cs + r * 132 + hf * 64, 1, g_k_f + ob);
    } else if (mode == 3) { // O-proj -> fp32 + bias
        int r = tid >> 1, hf = tid & 1;
        float* op = out + (size_t)(m0 + r) * D_ + n0 + hf * 64;
        const float* sp = cs + r * 132 + hf * 64;
        const float* bp = bias + n0 + hf * 64;
#pragma unroll
        for (int g = 0; g < 16; g++) {
            float4 v;
            v.x = sp[g * 4 + 0] + bp[g * 4 + 0];
            v.y = sp[g * 4 + 1] + bp[g * 4 + 1];
            v.z = sp[g * 4 + 2] + bp[g * 4 + 2];
            v.w = sp[g * 4 + 3] + bp[g * 4 + 3];
            *reinterpret_cast<float4*>(op + g * 4) = v;
        }
    } else {                // V -> fp16 single transposed [b,h,d,S]
        int dl = tid >> 1, sh = tid & 1;
        int dg = n0 + dl, hh = dg >> 6, dd = dg & 63, bb = m0 >> 11;
        size_t ob = ((size_t)(bb * 8 + hh) * 64 + dd) * (size_t)S_ + (m0 & 2047) + sh * 64;
        row64_h(cs + (sh * 64) * 132 + dl, 132, g_vt_f + ob);
    }
}

// ------------------------- attention (fp16) --------------------------------
// CTA = 128 q-rows x (b,h); 2 CTAs/SM. kv tiles of 64, 3-stage pipeline.
// Q fp16 hi/lo register-resident (2-pass QK vs single-fp16 K).
// P,V single fp16 (1-pass PV). Unnormalized O; register row sums.
#define AQ   0        /* Q hi 18432; lo at +18432 */
#define AK   36864    /* + buf*9216, buf 0..2 */
#define AV   64512    /* + buf*9216, buf 0..2 */
#define ASMB 92160

__global__ __launch_bounds__(256, 2) void attn_mma() {
    extern __shared__ char sm[];
    const int tid = threadIdx.x, lane = tid & 31, w = tid >> 5;
    const int qt = blockIdx.x, b = blockIdx.y >> 3, h = blockIdx.y & 7;
    const uint32_t sb = smem_u32(sm);

    const size_t qbase = (size_t)(b * S_ + qt * 128) * D_ + h * 64;
    const size_t vbase = (size_t)((b * 8 + h) * 64) * S_;

    {   // Q tile fp16 hi/lo, 128 rows x 64 d, pitch 144B
        int r = tid >> 1, sg = (tid & 1) * 4;
        uint32_t d = sb + AQ + r * 144 + sg * 16;
        const size_t so = qbase + (size_t)r * D_ + sg * 8;
#pragma unroll
        for (int j = 0; j < 4; j++) {
            CP_ASYNC(d + j * 16,         g_q_fh + so + j * 8);
            CP_ASYNC(d + 18432 + j * 16, g_q_fl + so + j * 8);
        }
    }
    auto load_kv = [&](int t, int buf) {
        int r = tid >> 2, sg = (tid & 3) * 2;
        {   // K single fp16: 64 rows x 64 d
            uint32_t d = sb + AK + buf * 9216 + r * 144 + sg * 16;
            const size_t so = (size_t)(b * S_ + t * 64 + r) * D_ + h * 64 + sg * 8;
#pragma unroll
            for (int j = 0; j < 2; j++) CP_ASYNC(d + j * 16, g_k_f + so + j * 8);
        }
        {   // V single fp16: 64 d rows x 64 kv cols
            uint32_t d = sb + AV + buf * 9216 + r * 144 + sg * 16;
            const size_t so = vbase + (size_t)r * S_ + t * 64 + sg * 8;
#pragma unroll
            for (int j = 0; j < 2; j++) CP_ASYNC(d + j * 16, g_vt_f + so + j * 8);
        }
    };
    load_kv(0, 0); CP_COMMIT();   // group0: Q + kv0
    load_kv(1, 1); CP_COMMIT();   // group1: kv1

    uint32_t qh[4][4], ql[4][4];
    float o[8][4];
#pragma unroll
    for (int i = 0; i < 8; i++)
#pragma unroll
        for (int j = 0; j < 4; j++) o[i][j] = 0.f;
    float rs0 = 0.f, rs1 = 0.f;

    const uint32_t qarow = sb + AQ + (uint32_t)(w * 16 + (lane & 15)) * 144 + (lane >> 4) * 16;
    const uint32_t krow  = (uint32_t)(((lane >> 4) & 1) * 8 + (lane & 7)) * 144 + ((lane >> 3) & 1) * 16;
    const float CEXP = 0.18033688011112042f;   // log2(e)/8

    for (int t = 0; t < 32; t++) {
        if (t < 30) CP_WAIT(1); else CP_WAIT(0);
        __syncthreads();
        if (t == 0) {   // Q fragments -> registers (once)
#pragma unroll
            for (int kk = 0; kk < 4; kk++) {
                ldsm4(qh[kk], qarow + kk * 32);
                ldsm4(ql[kk], qarow + kk * 32 + 18432);
            }
        }
        if (t + 2 < 32) { load_kv(t + 2, (t + 2) % 3); CP_COMMIT(); }
        const uint32_t kb = sb + AK + (t % 3) * 9216;
        const uint32_t vb = sb + AV + (t % 3) * 9216;

        // S = Q @ K^T : 2-pass (qh + ql) x single K
        float s[8][4];
#pragma unroll
        for (int i = 0; i < 8; i++)
#pragma unroll
            for (int j = 0; j < 4; j++) s[i][j] = 0.f;

#pragma unroll
        for (int kk = 0; kk < 4; kk++) {
#pragma unroll
            for (int nt2 = 0; nt2 < 4; nt2++) {
                uint32_t ba = kb + krow + nt2 * 16 * 144 + kk * 32;
                uint32_t bh[4];
                ldsm4(bh, ba);
                mma16816h(s[nt2 * 2],     qh[kk], &bh[0]);
                mma16816h(s[nt2 * 2],     ql[kk], &bh[0]);
                mma16816h(s[nt2 * 2 + 1], qh[kk], &bh[2]);
                mma16816h(s[nt2 * 2 + 1], ql[kk], &bh[2]);
            }
        }

        // exp -> single-fp16 P fragment -> 1-pass PV
#pragma unroll
        for (int kt = 0; kt < 4; kt++) {
            float e0 = fast_ex2(s[2*kt][0] * CEXP),   e1 = fast_ex2(s[2*kt][1] * CEXP);
            float e2 = fast_ex2(s[2*kt][2] * CEXP),   e3 = fast_ex2(s[2*kt][3] * CEXP);
            float e4 = fast_ex2(s[2*kt+1][0] * CEXP), e5 = fast_ex2(s[2*kt+1][1] * CEXP);
            float e6 = fast_ex2(s[2*kt+1][2] * CEXP), e7 = fast_ex2(s[2*kt+1][3] * CEXP);
            rs0 += e0 + e1 + e4 + e5;
            rs1 += e2 + e3 + e6 + e7;
            uint32_t p[4];
            p[0] = pack2h(e0, e1); p[1] = pack2h(e2, e3);
            p[2] = pack2h(e4, e5); p[3] = pack2h(e6, e7);
#pragma unroll
            for (int dt2 = 0; dt2 < 4; dt2++) {
                uint32_t va = vb + krow + dt2 * 16 * 144 + kt * 32;
                uint32_t vh[4];
                ldsm4(vh, va);
                mma16816h(o[dt2 * 2],     p, &vh[0]);
                mma16816h(o[dt2 * 2 + 1], p, &vh[2]);
            }
        }
    }

    rs0 += __shfl_xor_sync(0xffffffffu, rs0, 1);
    rs0 += __shfl_xor_sync(0xffffffffu, rs0, 2);
    rs1 += __shfl_xor_sync(0xffffffffu, rs1, 1);
    rs1 += __shfl_xor_sync(0xffffffffu, rs1, 2);
    const float i0 = 1.f / rs0, i1 = 1.f / rs1;

    size_t r0 = (size_t)(b * S_ + qt * 128 + w * 16 + (lane >> 2)) * D_ + h * 64 + 2 * (lane & 3);
#pragma unroll
    for (int dt = 0; dt < 8; dt++) {
        uint32_t uh, ul;
        split2(o[dt][0] * i0, o[dt][1] * i0, uh, ul);
        *reinterpret_cast<uint32_t*>(g_att_hi + r0 + dt * 8) = uh;
        *reinterpret_cast<uint32_t*>(g_att_lo + r0 + dt * 8) = ul;
        split2(o[dt][2] * i1, o[dt][3] * i1, uh, ul);
        *reinterpret_cast<uint32_t*>(g_att_hi + r0 + 8 * D_ + dt * 8) = uh;
        *reinterpret_cast<uint32_t*>(g_att_lo + r0 + 8 * D_ + dt * 8) = ul;
    }
}

// ------------------------- launch -----------------------------------------
extern "C" void kernel_launch(void* const* d_in, const int* in_sizes, int n_in,
                              void* d_out, int out_size) {
    const float* x  = (const float*)d_in[0];
    const float* Wq = (const float*)d_in[1];
    const float* Wk = (const float*)d_in[2];
    const float* Wv = (const float*)d_in[3];
    const float* Wo = (const float*)d_in[4];
    const float* bo = (const float*)d_in[5];
    float* out = (float*)d_out;

    cudaFuncSetAttribute(gemm_mma, cudaFuncAttributeMaxDynamicSharedMemorySize, GSM);
    cudaFuncSetAttribute(attn_mma, cudaFuncAttributeMaxDynamicSharedMemorySize, ASMB);

    cvt_x<<<(TOK * D_) / 1024, 256>>>(x);
    cvt_w<<<dim3(16, 16, 4), 256>>>(Wq, Wk, Wv, Wo);
    gemm_mma<<<dim3(TOK / 128, D_ / 128, 3), 256, GSM>>>(0, nullptr, nullptr);  // Q,K,V
    attn_mma<<<dim3(S_ / 128, B_ * 8), 256, ASMB>>>();
    gemm_mma<<<dim3(TOK / 128, D_ / 128, 1), 256, GSM>>>(3, bo, out);           // O-proj
}

// round 14
// speedup vs baseline: 5.2511x; 1.3050x over previous
#include <cuda_runtime.h>
#include <cuda_bf16.h>
#include <cuda_fp16.h>
#include <cstdint>

#define B_ 4
#define S_ 2048
#define D_ 512
#define TOK (B_*S_)

// ------------------------- device scratch ---------------------------------
__device__ __half g_x_fh[TOK*D_], g_x_fl[TOK*D_];     // x fp16 hi/lo
__device__ __half g_w_f[4*D_*D_];                     // W single fp16, [n][k]
__device__ __half g_q_f[TOK*D_];                      // Q single fp16
__device__ __half g_k_f[TOK*D_];                      // K single fp16
__device__ __half g_vt_f[TOK*D_];                     // V single fp16, [b,h,d,S]
__device__ __half g_att_fh[TOK*D_], g_att_fl[TOK*D_]; // attn out fp16 hi/lo

// ------------------------- PTX helpers ------------------------------------
__device__ __forceinline__ uint32_t smem_u32(const void* p) {
    uint32_t a;
    asm("{ .reg .u64 t; cvta.to.shared.u64 t, %1; cvt.u32.u64 %0, t; }"
        : "=r"(a) : "l"(p));
    return a;
}
#define CP_ASYNC(d, s) asm volatile("cp.async.cg.shared.global [%0], [%1], 16;" :: "r"(d), "l"(s) : "memory")
#define CP_COMMIT()    asm volatile("cp.async.commit_group;" ::: "memory")
#define CP_WAIT(n)     asm volatile("cp.async.wait_group %0;" :: "n"(n) : "memory")

__device__ __forceinline__ void ldsm4(uint32_t* r, uint32_t a) {
    asm volatile("ldmatrix.sync.aligned.m8n8.x4.shared.b16 {%0,%1,%2,%3}, [%4];"
        : "=r"(r[0]), "=r"(r[1]), "=r"(r[2]), "=r"(r[3]) : "r"(a));
}
__device__ __forceinline__ void mma16816h(float* c, const uint32_t* a, const uint32_t* b) {
    asm volatile("mma.sync.aligned.m16n8k16.row.col.f32.f16.f16.f32 "
        "{%0,%1,%2,%3}, {%4,%5,%6,%7}, {%8,%9}, {%0,%1,%2,%3};"
        : "+f"(c[0]), "+f"(c[1]), "+f"(c[2]), "+f"(c[3])
        : "r"(a[0]), "r"(a[1]), "r"(a[2]), "r"(a[3]), "r"(b[0]), "r"(b[1]));
}
__device__ __forceinline__ float fast_ex2(float x) {
    float y; asm("ex2.approx.f32 %0, %1;" : "=f"(y) : "f"(x)); return y;
}
__device__ __forceinline__ void split2h(float f0, float f1, uint32_t& h, uint32_t& l) {
    __half h0 = __float2half_rn(f0), h1 = __float2half_rn(f1);
    __half l0 = __float2half_rn(f0 - __half2float(h0));
    __half l1 = __float2half_rn(f1 - __half2float(h1));
    __half2 th = __halves2half2(h0, h1), tl = __halves2half2(l0, l1);
    h = *reinterpret_cast<uint32_t*>(&th);
    l = *reinterpret_cast<uint32_t*>(&tl);
}
__device__ __forceinline__ uint32_t pack2h(float x, float y) {
    __half2 t = __floats2half2_rn(x, y);
    return *reinterpret_cast<uint32_t*>(&t);
}
// 64 strided floats -> 64 fp16 hi + lo
__device__ __forceinline__ void row64_h_split(const float* src, int stride,
                                              __half* oh, __half* ol) {
#pragma unroll
    for (int g = 0; g < 8; g++) {
        uint32_t hh[4], ll[4];
#pragma unroll
        for (int p = 0; p < 4; p++)
            split2h(src[(g*8 + p*2) * stride], src[(g*8 + p*2 + 1) * stride], hh[p], ll[p]);
        *reinterpret_cast<uint4*>(oh + g*8) = make_uint4(hh[0], hh[1], hh[2], hh[3]);
        *reinterpret_cast<uint4*>(ol + g*8) = make_uint4(ll[0], ll[1], ll[2], ll[3]);
    }
}
// 64 strided floats -> 64 fp16 single
__device__ __forceinline__ void row64_h(const float* src, int stride, __half* o) {
#pragma unroll
    for (int g = 0; g < 8; g++) {
        uint32_t hh[4];
#pragma unroll
        for (int p = 0; p < 4; p++)
            hh[p] = pack2h(src[(g*8 + p*2) * stride], src[(g*8 + p*2 + 1) * stride]);
        *reinterpret_cast<uint4*>(o + g*8) = make_uint4(hh[0], hh[1], hh[2], hh[3]);
    }
}

// ------------------------- prep kernels -----------------------------------
__global__ __launch_bounds__(256) void cvt_x(const float* __restrict__ x) {
    size_t i = ((size_t)blockIdx.x * 256 + threadIdx.x) * 4;
    float4 v = *reinterpret_cast<const float4*>(x + i);
    uint32_t h0, l0, h1, l1;
    split2h(v.x, v.y, h0, l0);
    split2h(v.z, v.w, h1, l1);
    *reinterpret_cast<uint2*>(g_x_fh + i) = make_uint2(h0, h1);
    *reinterpret_cast<uint2*>(g_x_fl + i) = make_uint2(l0, l1);
}

__global__ __launch_bounds__(256) void cvt_w(const float* __restrict__ Wq,
                                             const float* __restrict__ Wk,
                                             const float* __restrict__ Wv,
                                             const float* __restrict__ Wo) {
    __shared__ float t[32][33];
    const int z = blockIdx.z;
    const float* W = (z == 0) ? Wq : (z == 1) ? Wk : (z == 2) ? Wv : Wo;
    const int k0 = blockIdx.x * 32, n0 = blockIdx.y * 32;
    const int tx = threadIdx.x & 31, ty = threadIdx.x >> 5;
#pragma unroll
    for (int r = 0; r < 4; r++)
        t[ty + r * 8][tx] = W[(size_t)(k0 + ty + r * 8) * D_ + n0 + tx];
    __syncthreads();
#pragma unroll
    for (int r = 0; r < 4; r++) {
        int nn = ty + r * 8;
        size_t oi = (size_t)z * D_ * D_ + (size_t)(n0 + nn) * D_ + k0 + tx;
        g_w_f[oi] = __float2half_rn(t[tx][nn]);
    }
}

// ------------------------- HMMA GEMM (fp16 2-pass) -------------------------
// C = A @ W: A fp16 hi/lo x W single fp16. Block 128x128, warp 64x32, k=32.
// smem/buf: Ah 10240 | Al 10240 | B 10240 (pitch 80B). Epilogue cs[128][132].
// modes: 0=Q(fp16) 1=K(fp16) 2=V(fp16 transposed) 3=O(fp32+bias)
#define GSM 67584

__global__ __launch_bounds__(256, 2) void gemm_mma(int mode_base,
                                                   const float* __restrict__ bias,
                                                   float* __restrict__ out) {
    extern __shared__ char sm[];
    const int tid = threadIdx.x, lane = tid & 31, w = tid >> 5;
    const int wm = w & 1, wn = w >> 1;
    const int mode = mode_base + blockIdx.z;
    const int m0 = blockIdx.x * 128, n0 = blockIdx.y * 128;
    const uint32_t sb = smem_u32(sm);

    const __half* Ah = ((mode < 3) ? g_x_fh : g_att_fh) + (size_t)m0 * D_;
    const __half* Al = ((mode < 3) ? g_x_fl : g_att_fl) + (size_t)m0 * D_;
    const __half* Bf = g_w_f + (size_t)mode * D_ * D_ + (size_t)n0 * D_;

    float acc[4][4][4];
#pragma unroll
    for (int i = 0; i < 4; i++)
#pragma unroll
        for (int j = 0; j < 4; j++)
#pragma unroll
            for (int k = 0; k < 4; k++) acc[i][j][k] = 0.f;

    const int lr = tid >> 1, half = tid & 1;
    auto load_chunk = [&](int buf, int k0) {
        uint32_t d = sb + buf * 30720 + lr * 80 + half * 32;
        const size_t so = (size_t)lr * D_ + k0 + half * 16;
#pragma unroll
        for (int j = 0; j < 2; j++) {
            CP_ASYNC(d + j * 16,         Ah + so + j * 8);
            CP_ASYNC(d + 10240 + j * 16, Al + so + j * 8);
            CP_ASYNC(d + 20480 + j * 16, Bf + so + j * 8);
        }
    };

    load_chunk(0, 0); CP_COMMIT();
    const uint32_t arow = (uint32_t)(wm * 64 + (lane & 15)) * 80 + (lane >> 4) * 16;
    const uint32_t brow = (uint32_t)(wn * 32 + ((lane >> 4) & 1) * 8 + (lane & 7)) * 80
                          + ((lane >> 3) & 1) * 16;

    for (int c = 0; c < 16; c++) {
        if (c < 15) { load_chunk((c + 1) & 1, (c + 1) * 32); CP_COMMIT(); CP_WAIT(1); }
        else CP_WAIT(0);
        __syncthreads();
        const uint32_t base = sb + (c & 1) * 30720;
#pragma unroll
        for (int kk = 0; kk < 2; kk++) {
            uint32_t bh[2][4];
#pragma unroll
            for (int nt2 = 0; nt2 < 2; nt2++)
                ldsm4(bh[nt2], base + 20480 + brow + nt2 * 16 * 80 + kk * 32);
#pragma unroll
            for (int mt = 0; mt < 4; mt++) {
                uint32_t aa = base + arow + mt * 16 * 80 + kk * 32;
                uint32_t ah[4], al[4];
                ldsm4(ah, aa);
                ldsm4(al, aa + 10240);
#pragma unroll
                for (int nt2 = 0; nt2 < 2; nt2++) {
                    mma16816h(acc[mt][nt2 * 2],     ah, &bh[nt2][0]);
                    mma16816h(acc[mt][nt2 * 2],     al, &bh[nt2][0]);
                    mma16816h(acc[mt][nt2 * 2 + 1], ah, &bh[nt2][2]);
                    mma16816h(acc[mt][nt2 * 2 + 1], al, &bh[nt2][2]);
                }
            }
        }
        __syncthreads();
    }

    // stage C into smem [128][132] f32
    float* cs = reinterpret_cast<float*>(sm);
    {
        const int rr = wm * 64 + (lane >> 2), cc = wn * 32 + 2 * (lane & 3);
#pragma unroll
        for (int mt = 0; mt < 4; mt++)
#pragma unroll
            for (int nt = 0; nt < 4; nt++) {
                int r0 = rr + mt * 16, c0 = cc + nt * 8;
                cs[r0 * 132 + c0]           = acc[mt][nt][0];
                cs[r0 * 132 + c0 + 1]       = acc[mt][nt][1];
                cs[(r0 + 8) * 132 + c0]     = acc[mt][nt][2];
                cs[(r0 + 8) * 132 + c0 + 1] = acc[mt][nt][3];
            }
    }
    __syncthreads();

    if (mode == 0 || mode == 1) {   // Q / K -> single fp16
        int r = tid >> 1, hf = tid & 1;
        size_t ob = (size_t)(m0 + r) * D_ + n0 + hf * 64;
        row64_h(cs + r * 132 + hf * 64, 1, (mode ? g_k_f : g_q_f) + ob);
    } else if (mode == 3) {         // O-proj -> fp32 + bias
        int r = tid >> 1, hf = tid & 1;
        float* op = out + (size_t)(m0 + r) * D_ + n0 + hf * 64;
        const float* sp = cs + r * 132 + hf * 64;
        const float* bp = bias + n0 + hf * 64;
#pragma unroll
        for (int g = 0; g < 16; g++) {
            float4 v;
            v.x = sp[g * 4 + 0] + bp[g * 4 + 0];
            v.y = sp[g * 4 + 1] + bp[g * 4 + 1];
            v.z = sp[g * 4 + 2] + bp[g * 4 + 2];
            v.w = sp[g * 4 + 3] + bp[g * 4 + 3];
            *reinterpret_cast<float4*>(op + g * 4) = v;
        }
    } else {                        // V -> fp16 transposed [b,h,d,S]
        int dl = tid >> 1, sh = tid & 1;
        int dg = n0 + dl, hh = dg >> 6, dd = dg & 63, bb = m0 >> 11;
        size_t ob = ((size_t)(bb * 8 + hh) * 64 + dd) * (size_t)S_ + (m0 & 2047) + sh * 64;
        row64_h(cs + (sh * 64) * 132 + dl, 132, g_vt_f + ob);
    }
}

// ------------------------- attention (fp16, 1-pass QK + 1-pass PV) ---------
// CTA = 128 q-rows x (b,h); 2 CTAs/SM. kv tiles of 64, 3-stage pipeline.
// Q single fp16 register-resident. Unnormalized O; register row sums.
#define AQ   0        /* Q 18432 */
#define AK   18432    /* + buf*9216, buf 0..2 */
#define AV   46080    /* + buf*9216, buf 0..2 */
#define ASMB 73728

__global__ __launch_bounds__(256, 2) void attn_mma() {
    extern __shared__ char sm[];
    const int tid = threadIdx.x, lane = tid & 31, w = tid >> 5;
    const int qt = blockIdx.x, b = blockIdx.y >> 3, h = blockIdx.y & 7;
    const uint32_t sb = smem_u32(sm);

    const size_t qbase = (size_t)(b * S_ + qt * 128) * D_ + h * 64;
    const size_t vbase = (size_t)((b * 8 + h) * 64) * S_;

    {   // Q tile single fp16, 128 rows x 64 d, pitch 144B
        int r = tid >> 1, sg = (tid & 1) * 4;
        uint32_t d = sb + AQ + r * 144 + sg * 16;
        const size_t so = qbase + (size_t)r * D_ + sg * 8;
#pragma unroll
        for (int j = 0; j < 4; j++) CP_ASYNC(d + j * 16, g_q_f + so + j * 8);
    }
    auto load_kv = [&](int t, int buf) {
        int r = tid >> 2, sg = (tid & 3) * 2;
        {   // K: 64 rows x 64 d
            uint32_t d = sb + AK + buf * 9216 + r * 144 + sg * 16;
            const size_t so = (size_t)(b * S_ + t * 64 + r) * D_ + h * 64 + sg * 8;
#pragma unroll
            for (int j = 0; j < 2; j++) CP_ASYNC(d + j * 16, g_k_f + so + j * 8);
        }
        {   // V: 64 d rows x 64 kv cols
            uint32_t d = sb + AV + buf * 9216 + r * 144 + sg * 16;
            const size_t so = vbase + (size_t)r * S_ + t * 64 + sg * 8;
#pragma unroll
            for (int j = 0; j < 2; j++) CP_ASYNC(d + j * 16, g_vt_f + so + j * 8);
        }
    };
    load_kv(0, 0); CP_COMMIT();   // group0: Q + kv0
    load_kv(1, 1); CP_COMMIT();   // group1: kv1

    uint32_t qh[4][4];
    float o[8][4];
#pragma unroll
    for (int i = 0; i < 8; i++)
#pragma unroll
        for (int j = 0; j < 4; j++) o[i][j] = 0.f;
    float rs0 = 0.f, rs1 = 0.f;

    const uint32_t qarow = sb + AQ + (uint32_t)(w * 16 + (lane & 15)) * 144 + (lane >> 4) * 16;
    const uint32_t krow  = (uint32_t)(((lane >> 4) & 1) * 8 + (lane & 7)) * 144 + ((lane >> 3) & 1) * 16;
    const float CEXP = 0.18033688011112042f;   // log2(e)/8

    for (int t = 0; t < 32; t++) {
        if (t < 30) CP_WAIT(1); else CP_WAIT(0);
        __syncthreads();
        if (t == 0) {   // Q fragments -> registers (once)
#pragma unroll
            for (int kk = 0; kk < 4; kk++) ldsm4(qh[kk], qarow + kk * 32);
        }
        if (t + 2 < 32) { load_kv(t + 2, (t + 2) % 3); CP_COMMIT(); }
        const uint32_t kb = sb + AK + (t % 3) * 9216;
        const uint32_t vb = sb + AV + (t % 3) * 9216;

        // S = Q @ K^T : 1-pass fp16
        float s[8][4];
#pragma unroll
        for (int i = 0; i < 8; i++)
#pragma unroll
            for (int j = 0; j < 4; j++) s[i][j] = 0.f;

#pragma unroll
        for (int kk = 0; kk < 4; kk++) {
#pragma unroll
            for (int nt2 = 0; nt2 < 4; nt2++) {
                uint32_t ba = kb + krow + nt2 * 16 * 144 + kk * 32;
                uint32_t bh[4];
                ldsm4(bh, ba);
                mma16816h(s[nt2 * 2],     qh[kk], &bh[0]);
                mma16816h(s[nt2 * 2 + 1], qh[kk], &bh[2]);
            }
        }

        // exp -> single-fp16 P fragment -> 1-pass PV
#pragma unroll
        for (int kt = 0; kt < 4; kt++) {
            float e0 = fast_ex2(s[2*kt][0] * CEXP),   e1 = fast_ex2(s[2*kt][1] * CEXP);
            float e2 = fast_ex2(s[2*kt][2] * CEXP),   e3 = fast_ex2(s[2*kt][3] * CEXP);
            float e4 = fast_ex2(s[2*kt+1][0] * CEXP), e5 = fast_ex2(s[2*kt+1][1] * CEXP);
            float e6 = fast_ex2(s[2*kt+1][2] * CEXP), e7 = fast_ex2(s[2*kt+1][3] * CEXP);
            rs0 += e0 + e1 + e4 + e5;
            rs1 += e2 + e3 + e6 + e7;
            uint32_t p[4];
            p[0] = pack2h(e0, e1); p[1] = pack2h(e2, e3);
            p[2] = pack2h(e4, e5); p[3] = pack2h(e6, e7);
#pragma unroll
            for (int dt2 = 0; dt2 < 4; dt2++) {
                uint32_t va = vb + krow + dt2 * 16 * 144 + kt * 32;
                uint32_t vh[4];
                ldsm4(vh, va);
                mma16816h(o[dt2 * 2],     p, &vh[0]);
                mma16816h(o[dt2 * 2 + 1], p, &vh[2]);
            }
        }
    }

    rs0 += __shfl_xor_sync(0xffffffffu, rs0, 1);
    rs0 += __shfl_xor_sync(0xffffffffu, rs0, 2);
    rs1 += __shfl_xor_sync(0xffffffffu, rs1, 1);
    rs1 += __shfl_xor_sync(0xffffffffu, rs1, 2);
    const float i0 = 1.f / rs0, i1 = 1.f / rs1;

    size_t r0 = (size_t)(b * S_ + qt * 128 + w * 16 + (lane >> 2)) * D_ + h * 64 + 2 * (lane & 3);
#pragma unroll
    for (int dt = 0; dt < 8; dt++) {
        uint32_t uh, ul;
        split2h(o[dt][0] * i0, o[dt][1] * i0, uh, ul);
        *reinterpret_cast<uint32_t*>(g_att_fh + r0 + dt * 8) = uh;
        *reinterpret_cast<uint32_t*>(g_att_fl + r0 + dt * 8) = ul;
        split2h(o[dt][2] * i1, o[dt][3] * i1, uh, ul);
        *reinterpret_cast<uint32_t*>(g_att_fh + r0 + 8 * D_ + dt * 8) = uh;
        *reinterpret_cast<uint32_t*>(g_att_fl + r0 + 8 * D_ + dt * 8) = ul;
    }
}

// ------------------------- launch -----------------------------------------
extern "C" void kernel_launch(void* const* d_in, const int* in_sizes, int n_in,
                              void* d_out, int out_size) {
    const float* x  = (const float*)d_in[0];
    const float* Wq = (const float*)d_in[1];
    const float* Wk = (const float*)d_in[2];
    const float* Wv = (const float*)d_in[3];
    const float* Wo = (const float*)d_in[4];
    const float* bo = (const float*)d_in[5];
    float* out = (float*)d_out;

    cudaFuncSetAttribute(gemm_mma, cudaFuncAttributeMaxDynamicSharedMemorySize, GSM);
    cudaFuncSetAttribute(attn_mma, cudaFuncAttributeMaxDynamicSharedMemorySize, ASMB);

    cvt_x<<<(TOK * D_) / 1024, 256>>>(x);
    cvt_w<<<dim3(16, 16, 4), 256>>>(Wq, Wk, Wv, Wo);
    gemm_mma<<<dim3(TOK / 128, D_ / 128, 3), 256, GSM>>>(0, nullptr, nullptr);  // Q,K,V
    attn_mma<<<dim3(S_ / 128, B_ * 8), 256, ASMB>>>();
    gemm_mma<<<dim3(TOK / 128, D_ / 128, 1), 256, GSM>>>(3, bo, out);           // O-proj
}